// round 3
// baseline (speedup 1.0000x reference)
#include <cuda_runtime.h>
#include <cstdint>

#define HIDDEN 1024
#define EPSF 1e-6f

typedef unsigned long long ull;

// Scratch (allocation-free rule: __device__ globals)
__device__ float g_Q[24 * 128 * 128];       // 1.5 MB: orthogonal rotation blocks
__device__ float g_Wrot[3072 * 1024];       // 12 MB: rotated weight (filt)

// ---------------------------------------------------------------------------
// Stage 1: Cayley. Q = (2+eps) * inv(I + S + eps I) - I,  S = 0.5(A - A^T).
// One CTA per 128x128 block (24 total). In-place Gauss-Jordan, no pivoting
// (I+S has SPD symmetric part -> stable). 256 threads: thread = (row, half).
// ---------------------------------------------------------------------------
__global__ void cayley_kernel(const float* __restrict__ qR,
                              const float* __restrict__ kR,
                              const float* __restrict__ vR) {
    extern __shared__ float a[];           // 128 x 129 (padded, conflict-free col writes)
    const int P = 129;
    const int idx  = blockIdx.x;           // 0..23
    const int proj = idx >> 3;
    const int n    = idx & 7;
    const float* src = (proj == 0 ? qR : (proj == 1 ? kR : vR)) + n * 128 * 128;

    const int tid = threadIdx.x;
    const int r   = tid & 127;
    const int h   = tid >> 7;              // column half 0/1
    const int c0  = h * 64;

    // Build M = I + S + eps I
    #pragma unroll 4
    for (int j = 0; j < 64; ++j) {
        int c = c0 + j;
        float v = 0.5f * (src[r * 128 + c] - src[c * 128 + r]);
        if (c == r) v += 1.0f + EPSF;
        a[r * P + c] = v;
    }
    __syncthreads();

    for (int k = 0; k < 128; ++k) {
        float piv    = a[k * P + k];
        float pivinv = 1.0f / piv;
        float f      = a[r * P + k];
        __syncthreads();                   // reads done before row k is scaled
        if (r == k) {
            #pragma unroll 4
            for (int j = 0; j < 64; ++j) a[k * P + c0 + j] *= pivinv;
            if (k >= c0 && k < c0 + 64) a[k * P + k] = pivinv;
        }
        __syncthreads();                   // row k scaled
        if (r != k) {
            #pragma unroll 8
            for (int j = 0; j < 64; ++j) {
                int c = c0 + j;
                a[r * P + c] = fmaf(-f, a[k * P + c], a[r * P + c]);
            }
            if (k >= c0 && k < c0 + 64) a[r * P + k] = -f * pivinv;
        }
        __syncthreads();                   // elimination done before next reads
    }

    // Q = (2+eps) * Minv - I
    float* dst = g_Q + idx * 16384;
    const float s = 2.0f + EPSF;
    #pragma unroll 4
    for (int j = 0; j < 64; ++j) {
        int c = c0 + j;
        float v = s * a[r * P + c];
        if (c == r) v -= 1.0f;
        dst[r * 128 + c] = v;
    }
}

// ---------------------------------------------------------------------------
// Stage 2: Wrot[o][n*128+c] = sum_b W[o][n*128+b] * Q[idx][b][c]
// grid.x = 24 (proj,n), grid.y = 8 (o-tile of 128 rows). 256 threads:
// thread = (c, o-half). W reads are warp-uniform (L1 broadcast).
// ---------------------------------------------------------------------------
__global__ void rotate_kernel(const float* __restrict__ W) {
    extern __shared__ float Qs[];          // 128*128 f32 = 64 KB
    const int idx   = blockIdx.x;
    const int proj  = idx >> 3;
    const int n     = idx & 7;
    const int obase = proj * 1024 + blockIdx.y * 128;
    const int cbase = n * 128;
    const int tid   = threadIdx.x;

    for (int i = tid; i < 128 * 128; i += 256) Qs[i] = g_Q[idx * 16384 + i];
    __syncthreads();

    const int c    = tid & 127;
    const int half = tid >> 7;
    const float* Wp = W + (size_t)obase * 1024 + cbase;
    float*       Op = g_Wrot + (size_t)obase * 1024 + cbase;

    for (int oc = half * 64; oc < half * 64 + 64; oc += 4) {
        float a0 = 0.f, a1 = 0.f, a2 = 0.f, a3 = 0.f;
        #pragma unroll 4
        for (int b = 0; b < 128; ++b) {
            float q = Qs[b * 128 + c];
            a0 = fmaf(Wp[(size_t)(oc + 0) * 1024 + b], q, a0);
            a1 = fmaf(Wp[(size_t)(oc + 1) * 1024 + b], q, a1);
            a2 = fmaf(Wp[(size_t)(oc + 2) * 1024 + b], q, a2);
            a3 = fmaf(Wp[(size_t)(oc + 3) * 1024 + b], q, a3);
        }
        Op[(size_t)(oc + 0) * 1024 + c] = a0;
        Op[(size_t)(oc + 1) * 1024 + c] = a1;
        Op[(size_t)(oc + 2) * 1024 + c] = a2;
        Op[(size_t)(oc + 3) * 1024 + c] = a3;
    }
}

// ---------------------------------------------------------------------------
// Stage 3: out[m][o] = dot(x[m,:], Wrot[o,:]) + bias[o]
// M=32768, N=3072, K=1024. Tile 128x128x16, 256 threads, 8x8 microtile,
// packed fp32x2 FMA (FFMA2) -> 2x the scalar FFMA rate on sm_103a.
// ---------------------------------------------------------------------------
#define BM 128
#define BN 128
#define BK 16
#define PA 132

__device__ __forceinline__ ull pack_dup(float x) {
    ull d;
    unsigned u = __float_as_uint(x);
    asm("mov.b64 %0, {%1, %1};" : "=l"(d) : "r"(u));
    return d;
}
__device__ __forceinline__ void unpack2(ull d, float& lo, float& hi) {
    unsigned ulo, uhi;
    asm("mov.b64 {%0, %1}, %2;" : "=r"(ulo), "=r"(uhi) : "l"(d));
    lo = __uint_as_float(ulo);
    hi = __uint_as_float(uhi);
}

__global__ __launch_bounds__(256, 2)
void gemm_kernel(const float* __restrict__ A,      // x  [32768,1024]
                 const float* __restrict__ bias,   // [3072]
                 float* __restrict__ C) {          // [32768,3072]
    __shared__ float As[BK * PA];
    __shared__ float Bs[BK * PA];
    const float* B = g_Wrot;                       // [3072,1024]

    const int tid = threadIdx.x;
    const int m0  = blockIdx.y * BM;
    const int n0  = blockIdx.x * BN;
    const int tr8 = (tid >> 4) * 8;
    const int tc8 = (tid & 15) * 8;

    ull acc[8][4];
    #pragma unroll
    for (int i = 0; i < 8; ++i)
        #pragma unroll
        for (int j = 0; j < 4; ++j) acc[i][j] = 0ull;

    const int lrow = tid >> 2;                     // 0..63
    const int lkq  = (tid & 3) * 4;                // 0,4,8,12
    const float* Ag = A + (size_t)(m0 + lrow) * 1024 + lkq;
    const float* Bg = B + (size_t)(n0 + lrow) * 1024 + lkq;

    for (int kt = 0; kt < 1024; kt += BK) {
        #pragma unroll
        for (int j = 0; j < 2; ++j) {
            const int row = lrow + j * 64;
            float4 av = *(const float4*)(Ag + (size_t)j * 64 * 1024 + kt);
            float4 bv = *(const float4*)(Bg + (size_t)j * 64 * 1024 + kt);
            As[(lkq + 0) * PA + row] = av.x;
            As[(lkq + 1) * PA + row] = av.y;
            As[(lkq + 2) * PA + row] = av.z;
            As[(lkq + 3) * PA + row] = av.w;
            Bs[(lkq + 0) * PA + row] = bv.x;
            Bs[(lkq + 1) * PA + row] = bv.y;
            Bs[(lkq + 2) * PA + row] = bv.z;
            Bs[(lkq + 3) * PA + row] = bv.w;
        }
        __syncthreads();

        #pragma unroll
        for (int kk = 0; kk < BK; ++kk) {
            const float* ap = &As[kk * PA + tr8];
            const float* bp = &Bs[kk * PA + tc8];
            float4 a0 = *(const float4*)(ap);
            float4 a1 = *(const float4*)(ap + 4);
            ull b0 = *(const ull*)(bp + 0);
            ull b1 = *(const ull*)(bp + 2);
            ull b2 = *(const ull*)(bp + 4);
            ull b3 = *(const ull*)(bp + 6);
            float av[8] = {a0.x, a0.y, a0.z, a0.w, a1.x, a1.y, a1.z, a1.w};
            #pragma unroll
            for (int i = 0; i < 8; ++i) {
                ull ad = pack_dup(av[i]);
                asm("fma.rn.f32x2 %0, %1, %2, %0;" : "+l"(acc[i][0]) : "l"(ad), "l"(b0));
                asm("fma.rn.f32x2 %0, %1, %2, %0;" : "+l"(acc[i][1]) : "l"(ad), "l"(b1));
                asm("fma.rn.f32x2 %0, %1, %2, %0;" : "+l"(acc[i][2]) : "l"(ad), "l"(b2));
                asm("fma.rn.f32x2 %0, %1, %2, %0;" : "+l"(acc[i][3]) : "l"(ad), "l"(b3));
            }
        }
        __syncthreads();
    }

    // Epilogue: unpack, add bias, vectorized stores
    float bj[8];
    #pragma unroll
    for (int j = 0; j < 8; ++j) bj[j] = bias[n0 + tc8 + j];

    #pragma unroll
    for (int i = 0; i < 8; ++i) {
        float v[8];
        #pragma unroll
        for (int j = 0; j < 4; ++j) unpack2(acc[i][j], v[2 * j], v[2 * j + 1]);
        float4 o0 = make_float4(v[0] + bj[0], v[1] + bj[1], v[2] + bj[2], v[3] + bj[3]);
        float4 o1 = make_float4(v[4] + bj[4], v[5] + bj[5], v[6] + bj[6], v[7] + bj[7]);
        float* cp = C + (size_t)(m0 + tr8 + i) * 3072 + n0 + tc8;
        *(float4*)(cp)     = o0;
        *(float4*)(cp + 4) = o1;
    }
}

// ---------------------------------------------------------------------------
extern "C" void kernel_launch(void* const* d_in, const int* in_sizes, int n_in,
                              void* d_out, int out_size) {
    const float* W    = (const float*)d_in[0];   // attn_weight [3072,1024]
    const float* bias = (const float*)d_in[1];   // [3072]
    const float* x    = (const float*)d_in[2];   // [8,4096,1024]
    const float* qR   = (const float*)d_in[3];
    const float* kR   = (const float*)d_in[4];
    const float* vR   = (const float*)d_in[5];
    float* out = (float*)d_out;                  // [8,4096,3072]

    cudaFuncSetAttribute(cayley_kernel,
                         cudaFuncAttributeMaxDynamicSharedMemorySize, 128 * 129 * 4);
    cudaFuncSetAttribute(rotate_kernel,
                         cudaFuncAttributeMaxDynamicSharedMemorySize, 128 * 128 * 4);

    cayley_kernel<<<24, 256, 128 * 129 * 4>>>(qR, kR, vR);
    rotate_kernel<<<dim3(24, 8), 256, 128 * 128 * 4>>>(W);
    gemm_kernel<<<dim3(3072 / BN, 32768 / BM), 256>>>(x, bias, out);
}

// round 6
// speedup vs baseline: 2.2990x; 2.2990x over previous
#include <cuda_runtime.h>
#include <cuda_bf16.h>
#include <cstdint>

typedef unsigned long long ull;
#define EPSF 1e-6f

__device__ float          g_Q[24 * 128 * 128];
__device__ __nv_bfloat16  g_Abf[(size_t)32768 * 2048];  // x split: hi cols 0..1023, lo 1024..2047
__device__ __nv_bfloat16  g_Bbf[(size_t)3072 * 2048];   // rotated W split

__device__ __forceinline__ uint32_t smem_u32(const void* p) {
    uint32_t a;
    asm("{ .reg .u64 t; cvta.to.shared.u64 t, %1; cvt.u32.u64 %0, t; }" : "=r"(a) : "l"(p));
    return a;
}
__device__ __forceinline__ void cpa16(uint32_t s, const void* g) {
    asm volatile("cp.async.cg.shared.global [%0], [%1], 16;" :: "r"(s), "l"(g));
}
#define CP_COMMIT() asm volatile("cp.async.commit_group;")
#define CP_WAIT2()  asm volatile("cp.async.wait_group 2;")

// swizzled byte offset of element (row, k) in a [128][32] bf16 tile, 64B rows.
// chunk(16B) index = (k>>3) ^ ((row>>1)&3): conflict-free for 8-row ldmatrix
// reads and for cp.async 16B stores.
#define OFFS(row, k) ((uint32_t)((row) * 64 + ((((k) >> 3) ^ (((row) >> 1) & 3)) << 4)))

#define LDSM4(r, ad) \
    asm volatile("ldmatrix.sync.aligned.m8n8.x4.shared.b16 {%0,%1,%2,%3}, [%4];" \
        : "=r"((r)[0]), "=r"((r)[1]), "=r"((r)[2]), "=r"((r)[3]) : "r"(ad))

#define MMA(cc, A, b0, b1) \
    asm volatile("mma.sync.aligned.m16n8k16.row.col.f32.bf16.bf16.f32 " \
        "{%0,%1,%2,%3},{%4,%5,%6,%7},{%8,%9},{%0,%1,%2,%3};" \
        : "+f"((cc)[0]), "+f"((cc)[1]), "+f"((cc)[2]), "+f"((cc)[3]) \
        : "r"((A)[0]), "r"((A)[1]), "r"((A)[2]), "r"((A)[3]), "r"(b0), "r"(b1))

// ===========================================================================
// prep: blocks 0-23 cayley (register-resident GJ), blocks 24+ convert x.
// ===========================================================================
__global__ __launch_bounds__(512)
void prep_kernel(const float* __restrict__ qR, const float* __restrict__ kR,
                 const float* __restrict__ vR, const float* __restrict__ x) {
    const int tid = threadIdx.x;
    if (blockIdx.x >= 24) {
        const float4* x4 = (const float4*)x;
        const size_t total = (size_t)32768 * 256;
        for (size_t i = (size_t)(blockIdx.x - 24) * 512 + tid; i < total;
             i += (size_t)1024 * 512) {
            float4 v = x4[i];
            __nv_bfloat16 h0 = __float2bfloat16_rn(v.x), h1 = __float2bfloat16_rn(v.y);
            __nv_bfloat16 h2 = __float2bfloat16_rn(v.z), h3 = __float2bfloat16_rn(v.w);
            __nv_bfloat162 hh0 = {h0, h1}, hh1 = {h2, h3};
            __nv_bfloat162 ll0 = {__float2bfloat16_rn(v.x - __bfloat162float(h0)),
                                  __float2bfloat16_rn(v.y - __bfloat162float(h1))};
            __nv_bfloat162 ll1 = {__float2bfloat16_rn(v.z - __bfloat162float(h2)),
                                  __float2bfloat16_rn(v.w - __bfloat162float(h3))};
            size_t m = i >> 8;
            int    c = (int)(i & 255) * 4;
            __nv_bfloat16* hp = &g_Abf[m * 2048 + c];
            __nv_bfloat16* lp = hp + 1024;
            ((__nv_bfloat162*)hp)[0] = hh0; ((__nv_bfloat162*)hp)[1] = hh1;
            ((__nv_bfloat162*)lp)[0] = ll0; ((__nv_bfloat162*)lp)[1] = ll1;
        }
        return;
    }
    // Cayley: Q = (2+eps)*inv(I+S+epsI) - I. Thread owns (row r, 32 cols).
    __shared__ float rowb[2][132];
    __shared__ float colb[2][128];
    const int idx  = blockIdx.x;
    const int proj = idx >> 3, n = idx & 7;
    const float* src = (proj == 0 ? qR : (proj == 1 ? kR : vR)) + n * 16384;
    const int r = tid & 127, q = tid >> 7, c0 = q * 32;

    float regs[32];
    #pragma unroll 8
    for (int j = 0; j < 32; ++j) {
        int c = c0 + j;
        float v = 0.5f * (src[r * 128 + c] - src[c * 128 + r]);
        if (c == r) v += 1.0f + EPSF;
        regs[j] = v;
    }
    if (r == 0) {
        #pragma unroll 8
        for (int j = 0; j < 32; ++j) rowb[0][c0 + j] = regs[j];
    }
    if (q == 0) colb[0][r] = regs[0];

    for (int k = 0; k < 128; ++k) {
        const int b = k & 1;
        __syncthreads();
        float pivinv = 1.0f / rowb[b][k];
        float f = colb[b][r];
        if (r == k) {
            #pragma unroll 8
            for (int j = 0; j < 32; ++j) regs[j] *= pivinv;
            if (q == (k >> 5)) regs[k & 31] = pivinv;
        } else {
            float t = f * pivinv;
            #pragma unroll 8
            for (int j = 0; j < 32; ++j) regs[j] = fmaf(-t, rowb[b][c0 + j], regs[j]);
            if (q == (k >> 5)) regs[k & 31] = -t;
        }
        if (k + 1 < 128) {
            const int nb = b ^ 1;
            if (r == k + 1) {
                #pragma unroll 8
                for (int j = 0; j < 32; ++j) rowb[nb][c0 + j] = regs[j];
            }
            if (q == ((k + 1) >> 5)) colb[nb][r] = regs[(k + 1) & 31];
        }
    }
    float* dst = g_Q + idx * 16384 + r * 128 + c0;
    const float s = 2.0f + EPSF;
    #pragma unroll 8
    for (int j = 0; j < 32; ++j) {
        float v = s * regs[j];
        if (c0 + j == r) v -= 1.0f;
        dst[j] = v;
    }
}

// ===========================================================================
// rotate: Wrot = W_block @ Q, written as bf16 hi/lo split.
// ===========================================================================
__global__ void rotate_kernel(const float* __restrict__ W) {
    extern __shared__ float Qs[];
    const int idx = blockIdx.x, proj = idx >> 3, n = idx & 7;
    const int obase = proj * 1024 + blockIdx.y * 128;
    const int cbase = n * 128;
    const int tid = threadIdx.x;
    for (int i = tid; i < 16384; i += 256) Qs[i] = g_Q[idx * 16384 + i];
    __syncthreads();
    const int c = tid & 127, half = tid >> 7;
    const float* Wp = W + (size_t)obase * 1024 + cbase;
    for (int oc = half * 64; oc < half * 64 + 64; oc += 4) {
        float acc[4] = {0.f, 0.f, 0.f, 0.f};
        #pragma unroll 4
        for (int b = 0; b < 128; ++b) {
            float qv = Qs[b * 128 + c];
            acc[0] = fmaf(Wp[(size_t)(oc + 0) * 1024 + b], qv, acc[0]);
            acc[1] = fmaf(Wp[(size_t)(oc + 1) * 1024 + b], qv, acc[1]);
            acc[2] = fmaf(Wp[(size_t)(oc + 2) * 1024 + b], qv, acc[2]);
            acc[3] = fmaf(Wp[(size_t)(oc + 3) * 1024 + b], qv, acc[3]);
        }
        #pragma unroll
        for (int u = 0; u < 4; ++u) {
            size_t o = obase + oc + u;
            __nv_bfloat16 h = __float2bfloat16_rn(acc[u]);
            g_Bbf[o * 2048 + cbase + c] = h;
            g_Bbf[o * 2048 + 1024 + cbase + c] =
                __float2bfloat16_rn(acc[u] - __bfloat162float(h));
        }
    }
}

// ===========================================================================
// gemm: bf16 mma.sync 3-term split. CTA 128x128, K chunks of 32, 3 stages.
// Stage layout: [Ahi 8K][Alo 8K][Bhi 8K][Blo 8K] = 32KB. 8 warps (2M x 4N),
// warp tile 64x32.
// ===========================================================================
#define STAGE_B 32768
#define GEMM_SMEM (3 * STAGE_B)

__global__ __launch_bounds__(256, 2)
void gemm_kernel(const float* __restrict__ bias, float* __restrict__ out) {
    extern __shared__ char smem[];
    const uint32_t sb = smem_u32(smem);
    const int tid = threadIdx.x, wid = tid >> 5, lane = tid & 31;
    const int m0 = blockIdx.y * 128, n0 = blockIdx.x * 128;
    const int wm = (wid >> 2) * 64, wn = (wid & 3) * 32;

    float c[4][4][4];
    #pragma unroll
    for (int i = 0; i < 4; ++i)
        #pragma unroll
        for (int j = 0; j < 4; ++j)
            #pragma unroll
            for (int t = 0; t < 4; ++t) c[i][j][t] = 0.f;

    // ---- cp.async stage loader ----
    const int lrow0 = tid >> 2;            // 0..63
    const int lkg   = tid & 3;             // 16B chunk
    const uint32_t so0 = OFFS(lrow0, lkg * 8);
    const uint32_t so1 = OFFS(lrow0 + 64, lkg * 8);
    const char* gA0 = (const char*)g_Abf + (size_t)(m0 + lrow0) * 4096 + lkg * 16;
    const char* gA1 = gA0 + (size_t)64 * 4096;
    const char* gB0 = (const char*)g_Bbf + (size_t)(n0 + lrow0) * 4096 + lkg * 16;
    const char* gB1 = gB0 + (size_t)64 * 4096;

#define ISSUE(kt) do { \
    if ((kt) < 32) { \
        uint32_t st = sb + ((kt) % 3) * STAGE_B; \
        size_t gk = (size_t)(kt) * 64; \
        cpa16(st + so0,         gA0 + gk); \
        cpa16(st + so1,         gA1 + gk); \
        cpa16(st +  8192 + so0, gA0 + gk + 2048); \
        cpa16(st +  8192 + so1, gA1 + gk + 2048); \
        cpa16(st + 16384 + so0, gB0 + gk); \
        cpa16(st + 16384 + so1, gB1 + gk); \
        cpa16(st + 24576 + so0, gB0 + gk + 2048); \
        cpa16(st + 24576 + so1, gB1 + gk + 2048); \
    } \
    CP_COMMIT(); \
} while (0)

    ISSUE(0);
    ISSUE(1);

    // ldmatrix lane geometry
    const int arow = wm + (lane & 7) + ((lane >> 3) & 1) * 8;   // + i*16
    const int akb  = ((lane >> 4) & 1) * 8;                     // + ks
    const int bnr  = wn + (lane & 7) + ((lane >> 4) & 1) * 8;   // + p*16
    const int bkb  = ((lane >> 3) & 1) * 8;                     // + ks

    for (int kt = 0; kt < 32; ++kt) {
        ISSUE(kt + 2);
        CP_WAIT2();
        __syncthreads();
        const uint32_t st  = sb + (kt % 3) * STAGE_B;
        const uint32_t stAh = st, stAl = st + 8192;
        const uint32_t stBh = st + 16384, stBl = st + 24576;

        #pragma unroll
        for (int ks = 0; ks < 32; ks += 16) {
            uint32_t a[4][4], b[2][4];
            // pass 1: Ahi x Bhi
            #pragma unroll
            for (int i = 0; i < 4; ++i) LDSM4(a[i], stAh + OFFS(arow + i * 16, ks + akb));
            #pragma unroll
            for (int p = 0; p < 2; ++p) LDSM4(b[p], stBh + OFFS(bnr + p * 16, ks + bkb));
            #pragma unroll
            for (int i = 0; i < 4; ++i) {
                MMA(c[i][0], a[i], b[0][0], b[0][1]);
                MMA(c[i][1], a[i], b[0][2], b[0][3]);
                MMA(c[i][2], a[i], b[1][0], b[1][1]);
                MMA(c[i][3], a[i], b[1][2], b[1][3]);
            }
            // pass 2: Alo x Bhi
            #pragma unroll
            for (int i = 0; i < 4; ++i) LDSM4(a[i], stAl + OFFS(arow + i * 16, ks + akb));
            #pragma unroll
            for (int i = 0; i < 4; ++i) {
                MMA(c[i][0], a[i], b[0][0], b[0][1]);
                MMA(c[i][1], a[i], b[0][2], b[0][3]);
                MMA(c[i][2], a[i], b[1][0], b[1][1]);
                MMA(c[i][3], a[i], b[1][2], b[1][3]);
            }
            // pass 3: Ahi x Blo
            #pragma unroll
            for (int i = 0; i < 4; ++i) LDSM4(a[i], stAh + OFFS(arow + i * 16, ks + akb));
            #pragma unroll
            for (int p = 0; p < 2; ++p) LDSM4(b[p], stBl + OFFS(bnr + p * 16, ks + bkb));
            #pragma unroll
            for (int i = 0; i < 4; ++i) {
                MMA(c[i][0], a[i], b[0][0], b[0][1]);
                MMA(c[i][1], a[i], b[0][2], b[0][3]);
                MMA(c[i][2], a[i], b[1][0], b[1][1]);
                MMA(c[i][3], a[i], b[1][2], b[1][3]);
            }
        }
        __syncthreads();
    }

    // ---- epilogue: direct coalesced-ish float2 stores + bias ----
    float2 bj[4];
    #pragma unroll
    for (int j = 0; j < 4; ++j)
        bj[j] = *(const float2*)(bias + n0 + wn + j * 8 + (lane & 3) * 2);

    #pragma unroll
    for (int i = 0; i < 4; ++i) {
        const int r = m0 + wm + i * 16 + (lane >> 2);
        #pragma unroll
        for (int j = 0; j < 4; ++j) {
            const int col = n0 + wn + j * 8 + (lane & 3) * 2;
            float2 v0 = {c[i][j][0] + bj[j].x, c[i][j][1] + bj[j].y};
            float2 v1 = {c[i][j][2] + bj[j].x, c[i][j][3] + bj[j].y};
            *(float2*)(out + (size_t)r * 3072 + col)       = v0;
            *(float2*)(out + (size_t)(r + 8) * 3072 + col) = v1;
        }
    }
}

// ---------------------------------------------------------------------------
extern "C" void kernel_launch(void* const* d_in, const int* in_sizes, int n_in,
                              void* d_out, int out_size) {
    const float* W    = (const float*)d_in[0];
    const float* bias = (const float*)d_in[1];
    const float* x    = (const float*)d_in[2];
    const float* qR   = (const float*)d_in[3];
    const float* kR   = (const float*)d_in[4];
    const float* vR   = (const float*)d_in[5];
    float* out = (float*)d_out;

    cudaFuncSetAttribute(rotate_kernel, cudaFuncAttributeMaxDynamicSharedMemorySize, 65536);
    cudaFuncSetAttribute(gemm_kernel,   cudaFuncAttributeMaxDynamicSharedMemorySize, GEMM_SMEM);

    prep_kernel<<<24 + 1024, 512>>>(qR, kR, vR, x);
    rotate_kernel<<<dim3(24, 8), 256, 65536>>>(W);
    gemm_kernel<<<dim3(24, 256), 256, GEMM_SMEM>>>(bias, out);
}

// round 7
// speedup vs baseline: 2.3479x; 1.0213x over previous
#include <cuda_runtime.h>
#include <cuda_bf16.h>
#include <cstdint>

typedef unsigned long long ull;
#define EPSF 1e-6f

__device__ float          g_Q[24 * 128 * 128];
__device__ __nv_bfloat16  g_Abf[(size_t)32768 * 2048];  // x split: hi cols 0..1023, lo 1024..2047
__device__ __nv_bfloat16  g_Bbf[(size_t)3072 * 2048];   // rotated W split

__device__ __forceinline__ uint32_t smem_u32(const void* p) {
    uint32_t a;
    asm("{ .reg .u64 t; cvta.to.shared.u64 t, %1; cvt.u32.u64 %0, t; }" : "=r"(a) : "l"(p));
    return a;
}
__device__ __forceinline__ void cpa16(uint32_t s, const void* g) {
    asm volatile("cp.async.cg.shared.global [%0], [%1], 16;" :: "r"(s), "l"(g));
}
#define CP_COMMIT() asm volatile("cp.async.commit_group;")
#define CP_WAIT2()  asm volatile("cp.async.wait_group 2;")

// swizzled byte offset of element (row, k) in a [128][32] bf16 tile, 64B rows.
#define OFFS(row, k) ((uint32_t)((row) * 64 + ((((k) >> 3) ^ (((row) >> 1) & 3)) << 4)))

#define LDSM4(r, ad) \
    asm volatile("ldmatrix.sync.aligned.m8n8.x4.shared.b16 {%0,%1,%2,%3}, [%4];" \
        : "=r"((r)[0]), "=r"((r)[1]), "=r"((r)[2]), "=r"((r)[3]) : "r"(ad))

#define MMA(cc, A, b0, b1) \
    asm volatile("mma.sync.aligned.m16n8k16.row.col.f32.bf16.bf16.f32 " \
        "{%0,%1,%2,%3},{%4,%5,%6,%7},{%8,%9},{%0,%1,%2,%3};" \
        : "+f"((cc)[0]), "+f"((cc)[1]), "+f"((cc)[2]), "+f"((cc)[3]) \
        : "r"((A)[0]), "r"((A)[1]), "r"((A)[2]), "r"((A)[3]), "r"(b0), "r"(b1))

// pack two f32 -> bf16x2 (lo element in low half)
#define PACKBF(d, flo, fhi) \
    asm("cvt.rn.bf16x2.f32 %0, %1, %2;" : "=r"(d) : "f"(fhi), "f"(flo))

// ===========================================================================
// prep: blocks 0-23 cayley (register-resident GJ), blocks 24+ convert x.
// Convert uses truncation split: hi = x & 0xFFFF0000 (PRMT pack), lo = x - hi
// (exact), lo -> bf16 rn. 12 ALU ops per float4 instead of ~24 CVTs.
// ===========================================================================
__global__ __launch_bounds__(512)
void prep_kernel(const float* __restrict__ qR, const float* __restrict__ kR,
                 const float* __restrict__ vR, const float* __restrict__ x) {
    const int tid = threadIdx.x;
    if (blockIdx.x >= 24) {
        const uint4* xv = (const uint4*)x;
        const size_t stride = (size_t)1024 * 512;
        // unit = 8 consecutive floats
        for (size_t u = (size_t)(blockIdx.x - 24) * 512 + tid;
             u < (size_t)32768 * 128; u += stride) {
            size_t m  = u >> 7;
            int    c8 = (int)(u & 127) * 8;
            uint4 a = xv[2 * u];
            uint4 b = xv[2 * u + 1];
            uint4 hv;
            hv.x = __byte_perm(a.x, a.y, 0x7632);
            hv.y = __byte_perm(a.z, a.w, 0x7632);
            hv.z = __byte_perm(b.x, b.y, 0x7632);
            hv.w = __byte_perm(b.z, b.w, 0x7632);
            float l0 = __uint_as_float(a.x) - __uint_as_float(a.x & 0xFFFF0000u);
            float l1 = __uint_as_float(a.y) - __uint_as_float(a.y & 0xFFFF0000u);
            float l2 = __uint_as_float(a.z) - __uint_as_float(a.z & 0xFFFF0000u);
            float l3 = __uint_as_float(a.w) - __uint_as_float(a.w & 0xFFFF0000u);
            float l4 = __uint_as_float(b.x) - __uint_as_float(b.x & 0xFFFF0000u);
            float l5 = __uint_as_float(b.y) - __uint_as_float(b.y & 0xFFFF0000u);
            float l6 = __uint_as_float(b.z) - __uint_as_float(b.z & 0xFFFF0000u);
            float l7 = __uint_as_float(b.w) - __uint_as_float(b.w & 0xFFFF0000u);
            uint4 lv;
            PACKBF(lv.x, l0, l1);
            PACKBF(lv.y, l2, l3);
            PACKBF(lv.z, l4, l5);
            PACKBF(lv.w, l6, l7);
            *(uint4*)(&g_Abf[m * 2048 + c8])        = hv;
            *(uint4*)(&g_Abf[m * 2048 + 1024 + c8]) = lv;
        }
        return;
    }
    // Cayley: Q = (2+eps)*inv(I+S+epsI) - I. Thread owns (row r, 32 cols).
    __shared__ float rowb[2][132];
    __shared__ float colb[2][128];
    const int idx  = blockIdx.x;
    const int proj = idx >> 3, n = idx & 7;
    const float* src = (proj == 0 ? qR : (proj == 1 ? kR : vR)) + n * 16384;
    const int r = tid & 127, q = tid >> 7, c0 = q * 32;

    float regs[32];
    #pragma unroll 8
    for (int j = 0; j < 32; ++j) {
        int c = c0 + j;
        float v = 0.5f * (src[r * 128 + c] - src[c * 128 + r]);
        if (c == r) v += 1.0f + EPSF;
        regs[j] = v;
    }
    if (r == 0) {
        #pragma unroll 8
        for (int j = 0; j < 32; ++j) rowb[0][c0 + j] = regs[j];
    }
    if (q == 0) colb[0][r] = regs[0];

    for (int k = 0; k < 128; ++k) {
        const int b = k & 1;
        __syncthreads();
        float pivinv = 1.0f / rowb[b][k];
        float f = colb[b][r];
        if (r == k) {
            #pragma unroll 8
            for (int j = 0; j < 32; ++j) regs[j] *= pivinv;
            if (q == (k >> 5)) regs[k & 31] = pivinv;
        } else {
            float t = f * pivinv;
            #pragma unroll 8
            for (int j = 0; j < 32; ++j) regs[j] = fmaf(-t, rowb[b][c0 + j], regs[j]);
            if (q == (k >> 5)) regs[k & 31] = -t;
        }
        if (k + 1 < 128) {
            const int nb = b ^ 1;
            if (r == k + 1) {
                #pragma unroll 8
                for (int j = 0; j < 32; ++j) rowb[nb][c0 + j] = regs[j];
            }
            if (q == ((k + 1) >> 5)) colb[nb][r] = regs[(k + 1) & 31];
        }
    }
    float* dst = g_Q + idx * 16384 + r * 128 + c0;
    const float s = 2.0f + EPSF;
    #pragma unroll 8
    for (int j = 0; j < 32; ++j) {
        float v = s * regs[j];
        if (c0 + j == r) v -= 1.0f;
        dst[j] = v;
    }
}

// ===========================================================================
// rotate: Wrot = W_block @ Q, written as bf16 hi/lo split.
// ===========================================================================
__global__ void rotate_kernel(const float* __restrict__ W) {
    extern __shared__ float Qs[];
    const int idx = blockIdx.x, proj = idx >> 3, n = idx & 7;
    const int obase = proj * 1024 + blockIdx.y * 128;
    const int cbase = n * 128;
    const int tid = threadIdx.x;
    for (int i = tid; i < 16384; i += 256) Qs[i] = g_Q[idx * 16384 + i];
    __syncthreads();
    const int c = tid & 127, half = tid >> 7;
    const float* Wp = W + (size_t)obase * 1024 + cbase;
    for (int oc = half * 64; oc < half * 64 + 64; oc += 4) {
        float acc[4] = {0.f, 0.f, 0.f, 0.f};
        #pragma unroll 4
        for (int b = 0; b < 128; ++b) {
            float qv = Qs[b * 128 + c];
            acc[0] = fmaf(Wp[(size_t)(oc + 0) * 1024 + b], qv, acc[0]);
            acc[1] = fmaf(Wp[(size_t)(oc + 1) * 1024 + b], qv, acc[1]);
            acc[2] = fmaf(Wp[(size_t)(oc + 2) * 1024 + b], qv, acc[2]);
            acc[3] = fmaf(Wp[(size_t)(oc + 3) * 1024 + b], qv, acc[3]);
        }
        #pragma unroll
        for (int u = 0; u < 4; ++u) {
            size_t o = obase + oc + u;
            float hv = __uint_as_float(__float_as_uint(acc[u]) & 0xFFFF0000u);
            g_Bbf[o * 2048 + cbase + c] =
                __ushort_as_bfloat16((unsigned short)(__float_as_uint(acc[u]) >> 16));
            g_Bbf[o * 2048 + 1024 + cbase + c] = __float2bfloat16_rn(acc[u] - hv);
        }
    }
}

// ===========================================================================
// gemm: bf16 mma.sync 3-term split. CTA 128x128, K chunks of 32, 3 stages.
// Pass order Ahi*Bhi, Ahi*Blo, Alo*Bhi keeps frags live: 12 LDSM4/ks not 16.
// ===========================================================================
#define STAGE_B 32768
#define GEMM_SMEM (3 * STAGE_B)

__global__ __launch_bounds__(256, 2)
void gemm_kernel(const float* __restrict__ bias, float* __restrict__ out) {
    extern __shared__ char smem[];
    const uint32_t sb = smem_u32(smem);
    const int tid = threadIdx.x, wid = tid >> 5, lane = tid & 31;
    const int m0 = blockIdx.y * 128, n0 = blockIdx.x * 128;
    const int wm = (wid >> 2) * 64, wn = (wid & 3) * 32;

    float c[4][4][4];
    #pragma unroll
    for (int i = 0; i < 4; ++i)
        #pragma unroll
        for (int j = 0; j < 4; ++j)
            #pragma unroll
            for (int t = 0; t < 4; ++t) c[i][j][t] = 0.f;

    const int lrow0 = tid >> 2;
    const int lkg   = tid & 3;
    const uint32_t so0 = OFFS(lrow0, lkg * 8);
    const uint32_t so1 = OFFS(lrow0 + 64, lkg * 8);
    const char* gA0 = (const char*)g_Abf + (size_t)(m0 + lrow0) * 4096 + lkg * 16;
    const char* gA1 = gA0 + (size_t)64 * 4096;
    const char* gB0 = (const char*)g_Bbf + (size_t)(n0 + lrow0) * 4096 + lkg * 16;
    const char* gB1 = gB0 + (size_t)64 * 4096;

#define ISSUE(kt) do { \
    if ((kt) < 32) { \
        uint32_t st = sb + ((kt) % 3) * STAGE_B; \
        size_t gk = (size_t)(kt) * 64; \
        cpa16(st + so0,         gA0 + gk); \
        cpa16(st + so1,         gA1 + gk); \
        cpa16(st +  8192 + so0, gA0 + gk + 2048); \
        cpa16(st +  8192 + so1, gA1 + gk + 2048); \
        cpa16(st + 16384 + so0, gB0 + gk); \
        cpa16(st + 16384 + so1, gB1 + gk); \
        cpa16(st + 24576 + so0, gB0 + gk + 2048); \
        cpa16(st + 24576 + so1, gB1 + gk + 2048); \
    } \
    CP_COMMIT(); \
} while (0)

    ISSUE(0);
    ISSUE(1);

    const int arow = wm + (lane & 7) + ((lane >> 3) & 1) * 8;
    const int akb  = ((lane >> 4) & 1) * 8;
    const int bnr  = wn + (lane & 7) + ((lane >> 4) & 1) * 8;
    const int bkb  = ((lane >> 3) & 1) * 8;

    for (int kt = 0; kt < 32; ++kt) {
        ISSUE(kt + 2);
        CP_WAIT2();
        __syncthreads();
        const uint32_t st   = sb + (kt % 3) * STAGE_B;
        const uint32_t stAh = st, stAl = st + 8192;
        const uint32_t stBh = st + 16384, stBl = st + 24576;

        #pragma unroll
        for (int ks = 0; ks < 32; ks += 16) {
            uint32_t a[4][4], bh[2][4], bl[2][4];
            #pragma unroll
            for (int i = 0; i < 4; ++i) LDSM4(a[i], stAh + OFFS(arow + i * 16, ks + akb));
            #pragma unroll
            for (int p = 0; p < 2; ++p) {
                LDSM4(bh[p], stBh + OFFS(bnr + p * 16, ks + bkb));
                LDSM4(bl[p], stBl + OFFS(bnr + p * 16, ks + bkb));
            }
            // pass 1: Ahi x Bhi
            #pragma unroll
            for (int i = 0; i < 4; ++i) {
                MMA(c[i][0], a[i], bh[0][0], bh[0][1]);
                MMA(c[i][1], a[i], bh[0][2], bh[0][3]);
                MMA(c[i][2], a[i], bh[1][0], bh[1][1]);
                MMA(c[i][3], a[i], bh[1][2], bh[1][3]);
            }
            // pass 2: Ahi x Blo (reuse A frags)
            #pragma unroll
            for (int i = 0; i < 4; ++i) {
                MMA(c[i][0], a[i], bl[0][0], bl[0][1]);
                MMA(c[i][1], a[i], bl[0][2], bl[0][3]);
                MMA(c[i][2], a[i], bl[1][0], bl[1][1]);
                MMA(c[i][3], a[i], bl[1][2], bl[1][3]);
            }
            // pass 3: Alo x Bhi (reuse B-hi frags)
            #pragma unroll
            for (int i = 0; i < 4; ++i) LDSM4(a[i], stAl + OFFS(arow + i * 16, ks + akb));
            #pragma unroll
            for (int i = 0; i < 4; ++i) {
                MMA(c[i][0], a[i], bh[0][0], bh[0][1]);
                MMA(c[i][1], a[i], bh[0][2], bh[0][3]);
                MMA(c[i][2], a[i], bh[1][0], bh[1][1]);
                MMA(c[i][3], a[i], bh[1][2], bh[1][3]);
            }
        }
        __syncthreads();
    }

    float2 bj[4];
    #pragma unroll
    for (int j = 0; j < 4; ++j)
        bj[j] = *(const float2*)(bias + n0 + wn + j * 8 + (lane & 3) * 2);

    #pragma unroll
    for (int i = 0; i < 4; ++i) {
        const int r = m0 + wm + i * 16 + (lane >> 2);
        #pragma unroll
        for (int j = 0; j < 4; ++j) {
            const int col = n0 + wn + j * 8 + (lane & 3) * 2;
            float2 v0 = {c[i][j][0] + bj[j].x, c[i][j][1] + bj[j].y};
            float2 v1 = {c[i][j][2] + bj[j].x, c[i][j][3] + bj[j].y};
            *(float2*)(out + (size_t)r * 3072 + col)       = v0;
            *(float2*)(out + (size_t)(r + 8) * 3072 + col) = v1;
        }
    }
}

// ---------------------------------------------------------------------------
extern "C" void kernel_launch(void* const* d_in, const int* in_sizes, int n_in,
                              void* d_out, int out_size) {
    const float* W    = (const float*)d_in[0];
    const float* bias = (const float*)d_in[1];
    const float* x    = (const float*)d_in[2];
    const float* qR   = (const float*)d_in[3];
    const float* kR   = (const float*)d_in[4];
    const float* vR   = (const float*)d_in[5];
    float* out = (float*)d_out;

    cudaFuncSetAttribute(rotate_kernel, cudaFuncAttributeMaxDynamicSharedMemorySize, 65536);
    cudaFuncSetAttribute(gemm_kernel,   cudaFuncAttributeMaxDynamicSharedMemorySize, GEMM_SMEM);

    prep_kernel<<<24 + 1024, 512>>>(qR, kR, vR, x);
    rotate_kernel<<<dim3(24, 8), 256, 65536>>>(W);
    gemm_kernel<<<dim3(24, 256), 256, GEMM_SMEM>>>(bias, out);
}

// round 8
// speedup vs baseline: 2.8871x; 1.2297x over previous
#include <cuda_runtime.h>
#include <cuda_bf16.h>
#include <cstdint>

typedef unsigned long long ull;
#define EPSF 1e-6f

__device__ float          g_Q[24 * 128 * 128];
__device__ __nv_bfloat16  g_Abf[(size_t)32768 * 2048];  // x split: hi cols 0..1023, lo 1024..2047
__device__ __nv_bfloat16  g_Bbf[(size_t)3072 * 2048];   // rotated W split

__device__ __forceinline__ uint32_t smem_u32(const void* p) {
    uint32_t a;
    asm("{ .reg .u64 t; cvta.to.shared.u64 t, %1; cvt.u32.u64 %0, t; }" : "=r"(a) : "l"(p));
    return a;
}
__device__ __forceinline__ void cpa16(uint32_t s, const void* g) {
    asm volatile("cp.async.cg.shared.global [%0], [%1], 16;" :: "r"(s), "l"(g));
}
#define CP_COMMIT() asm volatile("cp.async.commit_group;")
#define CP_WAIT2()  asm volatile("cp.async.wait_group 2;")

// swizzled byte offset of element (row, k) in a [128][32] bf16 tile, 64B rows.
#define OFFS(row, k) ((uint32_t)((row) * 64 + ((((k) >> 3) ^ (((row) >> 1) & 3)) << 4)))

#define LDSM4(r, ad) \
    asm volatile("ldmatrix.sync.aligned.m8n8.x4.shared.b16 {%0,%1,%2,%3}, [%4];" \
        : "=r"((r)[0]), "=r"((r)[1]), "=r"((r)[2]), "=r"((r)[3]) : "r"(ad))

#define MMA(cc, A, b0, b1) \
    asm volatile("mma.sync.aligned.m16n8k16.row.col.f32.bf16.bf16.f32 " \
        "{%0,%1,%2,%3},{%4,%5,%6,%7},{%8,%9},{%0,%1,%2,%3};" \
        : "+f"((cc)[0]), "+f"((cc)[1]), "+f"((cc)[2]), "+f"((cc)[3]) \
        : "r"((A)[0]), "r"((A)[1]), "r"((A)[2]), "r"((A)[3]), "r"(b0), "r"(b1))

#define PACKBF(d, flo, fhi) \
    asm("cvt.rn.bf16x2.f32 %0, %1, %2;" : "=r"(d) : "f"(fhi), "f"(flo))

// ===========================================================================
// prep: blocks 0-23 cayley (static-index register GJ), blocks 24+ convert x.
// ===========================================================================
__global__ __launch_bounds__(512)
void prep_kernel(const float* __restrict__ qR, const float* __restrict__ kR,
                 const float* __restrict__ vR, const float* __restrict__ x) {
    const int tid = threadIdx.x;
    if (blockIdx.x >= 24) {
        const uint4* xv = (const uint4*)x;
        const size_t stride = (size_t)1024 * 512;
        for (size_t u = (size_t)(blockIdx.x - 24) * 512 + tid;
             u < (size_t)32768 * 128; u += stride) {
            size_t m  = u >> 7;
            int    c8 = (int)(u & 127) * 8;
            uint4 a = xv[2 * u];
            uint4 b = xv[2 * u + 1];
            uint4 hv;
            hv.x = __byte_perm(a.x, a.y, 0x7632);
            hv.y = __byte_perm(a.z, a.w, 0x7632);
            hv.z = __byte_perm(b.x, b.y, 0x7632);
            hv.w = __byte_perm(b.z, b.w, 0x7632);
            float l0 = __uint_as_float(a.x) - __uint_as_float(a.x & 0xFFFF0000u);
            float l1 = __uint_as_float(a.y) - __uint_as_float(a.y & 0xFFFF0000u);
            float l2 = __uint_as_float(a.z) - __uint_as_float(a.z & 0xFFFF0000u);
            float l3 = __uint_as_float(a.w) - __uint_as_float(a.w & 0xFFFF0000u);
            float l4 = __uint_as_float(b.x) - __uint_as_float(b.x & 0xFFFF0000u);
            float l5 = __uint_as_float(b.y) - __uint_as_float(b.y & 0xFFFF0000u);
            float l6 = __uint_as_float(b.z) - __uint_as_float(b.z & 0xFFFF0000u);
            float l7 = __uint_as_float(b.w) - __uint_as_float(b.w & 0xFFFF0000u);
            uint4 lv;
            PACKBF(lv.x, l0, l1);
            PACKBF(lv.y, l2, l3);
            PACKBF(lv.z, l4, l5);
            PACKBF(lv.w, l6, l7);
            *(uint4*)(&g_Abf[m * 2048 + c8])        = hv;
            *(uint4*)(&g_Abf[m * 2048 + 1024 + c8]) = lv;
        }
        return;
    }
    // Cayley: Q = (2+eps)*inv(I+S+epsI) - I. Thread owns (row r, cols c0..c0+31).
    // All regs[] indices are compile-time constants (no local-mem demotion).
    __shared__ float rowb[2][132];
    __shared__ float colb[2][128];
    const int idx  = blockIdx.x;
    const int proj = idx >> 3, n = idx & 7;
    const float* src = (proj == 0 ? qR : (proj == 1 ? kR : vR)) + n * 16384;
    const int r = tid & 127, q = tid >> 7, c0 = q * 32;

    float regs[32];
    #pragma unroll
    for (int j = 0; j < 32; ++j) {
        int c = c0 + j;
        float v = 0.5f * (src[r * 128 + c] - src[c * 128 + r]);
        if (c == r) v += 1.0f + EPSF;
        regs[j] = v;
    }
    if (r == 0) {
        #pragma unroll
        for (int j = 0; j < 32; ++j) rowb[0][c0 + j] = regs[j];
    }
    if (q == 0) colb[0][r] = regs[0];   // column 0 = regs[0] of quarter 0

    for (int k = 0; k < 128; ++k) {
        const int b = k & 1, nb = b ^ 1;
        __syncthreads();
        const float pivinv = 1.0f / rowb[b][k];
        const float f      = colb[b][r];
        const float t      = f * pivinv;
        const bool  isPiv  = (r == k);
        #pragma unroll
        for (int j = 0; j < 32; ++j) {
            const int c = c0 + j;
            float v;
            if (isPiv) v = regs[j] * pivinv;
            else       v = fmaf(-t, rowb[b][c], regs[j]);
            if (c == k) v = isPiv ? pivinv : -t;
            regs[j] = v;
            if (c == k + 1)  colb[nb][r] = v;       // never true at k=127 (c<=127)
            if (r == k + 1)  rowb[nb][c] = v;       // never true at k=127
        }
    }
    float* dst = g_Q + idx * 16384 + r * 128 + c0;
    const float s = 2.0f + EPSF;
    #pragma unroll
    for (int j = 0; j < 32; ++j) {
        float v = s * regs[j];
        if (c0 + j == r) v -= 1.0f;
        dst[j] = v;
    }
}

// ===========================================================================
// rotate: Wrot = W_block @ Q, written as bf16 hi/lo split (truncation split).
// ===========================================================================
__global__ void rotate_kernel(const float* __restrict__ W) {
    extern __shared__ float Qs[];
    const int idx = blockIdx.x, proj = idx >> 3, n = idx & 7;
    const int obase = proj * 1024 + blockIdx.y * 128;
    const int cbase = n * 128;
    const int tid = threadIdx.x;
    for (int i = tid; i < 16384; i += 256) Qs[i] = g_Q[idx * 16384 + i];
    __syncthreads();
    const int c = tid & 127, half = tid >> 7;
    const float* Wp = W + (size_t)obase * 1024 + cbase;
    for (int oc = half * 64; oc < half * 64 + 64; oc += 4) {
        float acc[4] = {0.f, 0.f, 0.f, 0.f};
        #pragma unroll 4
        for (int b = 0; b < 128; ++b) {
            float qv = Qs[b * 128 + c];
            acc[0] = fmaf(Wp[(size_t)(oc + 0) * 1024 + b], qv, acc[0]);
            acc[1] = fmaf(Wp[(size_t)(oc + 1) * 1024 + b], qv, acc[1]);
            acc[2] = fmaf(Wp[(size_t)(oc + 2) * 1024 + b], qv, acc[2]);
            acc[3] = fmaf(Wp[(size_t)(oc + 3) * 1024 + b], qv, acc[3]);
        }
        #pragma unroll
        for (int u = 0; u < 4; ++u) {
            size_t o = obase + oc + u;
            float hv = __uint_as_float(__float_as_uint(acc[u]) & 0xFFFF0000u);
            g_Bbf[o * 2048 + cbase + c] =
                __ushort_as_bfloat16((unsigned short)(__float_as_uint(acc[u]) >> 16));
            g_Bbf[o * 2048 + 1024 + cbase + c] = __float2bfloat16_rn(acc[u] - hv);
        }
    }
}

// ===========================================================================
// gemm: bf16 mma.sync 3-term split. CTA 128x128, K chunks of 32, 3 stages.
// ===========================================================================
#define STAGE_B 32768
#define GEMM_SMEM (3 * STAGE_B)

__global__ __launch_bounds__(256, 2)
void gemm_kernel(const float* __restrict__ bias, float* __restrict__ out) {
    extern __shared__ char smem[];
    const uint32_t sb = smem_u32(smem);
    const int tid = threadIdx.x, wid = tid >> 5, lane = tid & 31;
    const int m0 = blockIdx.y * 128, n0 = blockIdx.x * 128;
    const int wm = (wid >> 2) * 64, wn = (wid & 3) * 32;

    float c[4][4][4];
    #pragma unroll
    for (int i = 0; i < 4; ++i)
        #pragma unroll
        for (int j = 0; j < 4; ++j)
            #pragma unroll
            for (int t = 0; t < 4; ++t) c[i][j][t] = 0.f;

    const int lrow0 = tid >> 2;
    const int lkg   = tid & 3;
    const uint32_t so0 = OFFS(lrow0, lkg * 8);
    const uint32_t so1 = OFFS(lrow0 + 64, lkg * 8);
    const char* gA0 = (const char*)g_Abf + (size_t)(m0 + lrow0) * 4096 + lkg * 16;
    const char* gA1 = gA0 + (size_t)64 * 4096;
    const char* gB0 = (const char*)g_Bbf + (size_t)(n0 + lrow0) * 4096 + lkg * 16;
    const char* gB1 = gB0 + (size_t)64 * 4096;

#define ISSUE(kt) do { \
    if ((kt) < 32) { \
        uint32_t st = sb + ((kt) % 3) * STAGE_B; \
        size_t gk = (size_t)(kt) * 64; \
        cpa16(st + so0,         gA0 + gk); \
        cpa16(st + so1,         gA1 + gk); \
        cpa16(st +  8192 + so0, gA0 + gk + 2048); \
        cpa16(st +  8192 + so1, gA1 + gk + 2048); \
        cpa16(st + 16384 + so0, gB0 + gk); \
        cpa16(st + 16384 + so1, gB1 + gk); \
        cpa16(st + 24576 + so0, gB0 + gk + 2048); \
        cpa16(st + 24576 + so1, gB1 + gk + 2048); \
    } \
    CP_COMMIT(); \
} while (0)

    ISSUE(0);
    ISSUE(1);

    const int arow = wm + (lane & 7) + ((lane >> 3) & 1) * 8;
    const int akb  = ((lane >> 4) & 1) * 8;
    const int bnr  = wn + (lane & 7) + ((lane >> 4) & 1) * 8;
    const int bkb  = ((lane >> 3) & 1) * 8;

    for (int kt = 0; kt < 32; ++kt) {
        ISSUE(kt + 2);
        CP_WAIT2();
        __syncthreads();
        const uint32_t st   = sb + (kt % 3) * STAGE_B;
        const uint32_t stAh = st, stAl = st + 8192;
        const uint32_t stBh = st + 16384, stBl = st + 24576;

        #pragma unroll
        for (int ks = 0; ks < 32; ks += 16) {
            uint32_t a[4][4], bh[2][4], bl[2][4];
            #pragma unroll
            for (int i = 0; i < 4; ++i) LDSM4(a[i], stAh + OFFS(arow + i * 16, ks + akb));
            #pragma unroll
            for (int p = 0; p < 2; ++p) {
                LDSM4(bh[p], stBh + OFFS(bnr + p * 16, ks + bkb));
                LDSM4(bl[p], stBl + OFFS(bnr + p * 16, ks + bkb));
            }
            #pragma unroll
            for (int i = 0; i < 4; ++i) {
                MMA(c[i][0], a[i], bh[0][0], bh[0][1]);
                MMA(c[i][1], a[i], bh[0][2], bh[0][3]);
                MMA(c[i][2], a[i], bh[1][0], bh[1][1]);
                MMA(c[i][3], a[i], bh[1][2], bh[1][3]);
            }
            #pragma unroll
            for (int i = 0; i < 4; ++i) {
                MMA(c[i][0], a[i], bl[0][0], bl[0][1]);
                MMA(c[i][1], a[i], bl[0][2], bl[0][3]);
                MMA(c[i][2], a[i], bl[1][0], bl[1][1]);
                MMA(c[i][3], a[i], bl[1][2], bl[1][3]);
            }
            #pragma unroll
            for (int i = 0; i < 4; ++i) LDSM4(a[i], stAl + OFFS(arow + i * 16, ks + akb));
            #pragma unroll
            for (int i = 0; i < 4; ++i) {
                MMA(c[i][0], a[i], bh[0][0], bh[0][1]);
                MMA(c[i][1], a[i], bh[0][2], bh[0][3]);
                MMA(c[i][2], a[i], bh[1][0], bh[1][1]);
                MMA(c[i][3], a[i], bh[1][2], bh[1][3]);
            }
        }
        __syncthreads();
    }

    float2 bj[4];
    #pragma unroll
    for (int j = 0; j < 4; ++j)
        bj[j] = *(const float2*)(bias + n0 + wn + j * 8 + (lane & 3) * 2);

    #pragma unroll
    for (int i = 0; i < 4; ++i) {
        const int r = m0 + wm + i * 16 + (lane >> 2);
        #pragma unroll
        for (int j = 0; j < 4; ++j) {
            const int col = n0 + wn + j * 8 + (lane & 3) * 2;
            float2 v0 = {c[i][j][0] + bj[j].x, c[i][j][1] + bj[j].y};
            float2 v1 = {c[i][j][2] + bj[j].x, c[i][j][3] + bj[j].y};
            *(float2*)(out + (size_t)r * 3072 + col)       = v0;
            *(float2*)(out + (size_t)(r + 8) * 3072 + col) = v1;
        }
    }
}

// ---------------------------------------------------------------------------
extern "C" void kernel_launch(void* const* d_in, const int* in_sizes, int n_in,
                              void* d_out, int out_size) {
    const float* W    = (const float*)d_in[0];
    const float* bias = (const float*)d_in[1];
    const float* x    = (const float*)d_in[2];
    const float* qR   = (const float*)d_in[3];
    const float* kR   = (const float*)d_in[4];
    const float* vR   = (const float*)d_in[5];
    float* out = (float*)d_out;

    cudaFuncSetAttribute(rotate_kernel, cudaFuncAttributeMaxDynamicSharedMemorySize, 65536);
    cudaFuncSetAttribute(gemm_kernel,   cudaFuncAttributeMaxDynamicSharedMemorySize, GEMM_SMEM);

    prep_kernel<<<24 + 1024, 512>>>(qR, kR, vR, x);
    rotate_kernel<<<dim3(24, 8), 256, 65536>>>(W);
    gemm_kernel<<<dim3(24, 256), 256, GEMM_SMEM>>>(bias, out);
}

// round 9
// speedup vs baseline: 3.1227x; 1.0816x over previous
#include <cuda_runtime.h>
#include <cuda_bf16.h>
#include <cstdint>

typedef unsigned long long ull;
#define EPSF 1e-6f

__device__ float          g_Q[24 * 128 * 128];
__device__ __nv_bfloat16  g_Abf[(size_t)32768 * 2048];  // x split: hi cols 0..1023, lo 1024..2047
__device__ __nv_bfloat16  g_Bbf[(size_t)3072 * 2048];   // rotated W split

__device__ __forceinline__ uint32_t smem_u32(const void* p) {
    uint32_t a;
    asm("{ .reg .u64 t; cvta.to.shared.u64 t, %1; cvt.u32.u64 %0, t; }" : "=r"(a) : "l"(p));
    return a;
}
__device__ __forceinline__ void cpa16(uint32_t s, const void* g) {
    asm volatile("cp.async.cg.shared.global [%0], [%1], 16;" :: "r"(s), "l"(g));
}
#define CP_COMMIT() asm volatile("cp.async.commit_group;")

// swizzled byte offset of element (row, k) in a [128][32] bf16 tile, 64B rows.
#define OFFS(row, k) ((uint32_t)((row) * 64 + ((((k) >> 3) ^ (((row) >> 1) & 3)) << 4)))

#define LDSM4(r, ad) \
    asm volatile("ldmatrix.sync.aligned.m8n8.x4.shared.b16 {%0,%1,%2,%3}, [%4];" \
        : "=r"((r)[0]), "=r"((r)[1]), "=r"((r)[2]), "=r"((r)[3]) : "r"(ad))

#define MMA(cc, A, b0, b1) \
    asm volatile("mma.sync.aligned.m16n8k16.row.col.f32.bf16.bf16.f32 " \
        "{%0,%1,%2,%3},{%4,%5,%6,%7},{%8,%9},{%0,%1,%2,%3};" \
        : "+f"((cc)[0]), "+f"((cc)[1]), "+f"((cc)[2]), "+f"((cc)[3]) \
        : "r"((A)[0]), "r"((A)[1]), "r"((A)[2]), "r"((A)[3]), "r"(b0), "r"(b1))

#define PACKBF(d, flo, fhi) \
    asm("cvt.rn.bf16x2.f32 %0, %1, %2;" : "=r"(d) : "f"(fhi), "f"(flo))

// ===========================================================================
// cayley: Q = (2+eps)*inv(I+S+epsI) - I. Static-index register GJ.
// ===========================================================================
__global__ __launch_bounds__(512)
void cayley_kernel(const float* __restrict__ qR, const float* __restrict__ kR,
                   const float* __restrict__ vR) {
    const int tid = threadIdx.x;
    __shared__ float rowb[2][132];
    __shared__ float colb[2][128];
    const int idx  = blockIdx.x;
    const int proj = idx >> 3, n = idx & 7;
    const float* src = (proj == 0 ? qR : (proj == 1 ? kR : vR)) + n * 16384;
    const int r = tid & 127, q = tid >> 7, c0 = q * 32;

    float regs[32];
    #pragma unroll
    for (int j = 0; j < 32; ++j) {
        int c = c0 + j;
        float v = 0.5f * (src[r * 128 + c] - src[c * 128 + r]);
        if (c == r) v += 1.0f + EPSF;
        regs[j] = v;
    }
    if (r == 0) {
        #pragma unroll
        for (int j = 0; j < 32; ++j) rowb[0][c0 + j] = regs[j];
    }
    if (q == 0) colb[0][r] = regs[0];

    for (int k = 0; k < 128; ++k) {
        const int b = k & 1, nb = b ^ 1;
        __syncthreads();
        const float pivinv = 1.0f / rowb[b][k];
        const float f      = colb[b][r];
        const float t      = f * pivinv;
        const bool  isPiv  = (r == k);
        #pragma unroll
        for (int j = 0; j < 32; ++j) {
            const int c = c0 + j;
            float v;
            if (isPiv) v = regs[j] * pivinv;
            else       v = fmaf(-t, rowb[b][c], regs[j]);
            if (c == k) v = isPiv ? pivinv : -t;
            regs[j] = v;
            if (c == k + 1)  colb[nb][r] = v;
            if (r == k + 1)  rowb[nb][c] = v;
        }
    }
    float* dst = g_Q + idx * 16384 + r * 128 + c0;
    const float s = 2.0f + EPSF;
    #pragma unroll
    for (int j = 0; j < 32; ++j) {
        float v = s * regs[j];
        if (c0 + j == r) v -= 1.0f;
        dst[j] = v;
    }
}

// ===========================================================================
// work: blocks 0-191 rotate (needs g_Q), blocks 192+ convert x.
// Both depend only on cayley -> run concurrently in one launch.
// ===========================================================================
#define CONV_BLKS 896
__global__ __launch_bounds__(256)
void work_kernel(const float* __restrict__ W, const float* __restrict__ x) {
    const int tid = threadIdx.x;
    if (blockIdx.x >= 192) {
        // ---- convert x -> bf16 truncation split ----
        const uint4* xv = (const uint4*)x;
        const size_t stride = (size_t)CONV_BLKS * 256;
        for (size_t u = (size_t)(blockIdx.x - 192) * 256 + tid;
             u < (size_t)32768 * 128; u += stride) {
            size_t m  = u >> 7;
            int    c8 = (int)(u & 127) * 8;
            uint4 a = xv[2 * u];
            uint4 b = xv[2 * u + 1];
            uint4 hv;
            hv.x = __byte_perm(a.x, a.y, 0x7632);
            hv.y = __byte_perm(a.z, a.w, 0x7632);
            hv.z = __byte_perm(b.x, b.y, 0x7632);
            hv.w = __byte_perm(b.z, b.w, 0x7632);
            float l0 = __uint_as_float(a.x) - __uint_as_float(a.x & 0xFFFF0000u);
            float l1 = __uint_as_float(a.y) - __uint_as_float(a.y & 0xFFFF0000u);
            float l2 = __uint_as_float(a.z) - __uint_as_float(a.z & 0xFFFF0000u);
            float l3 = __uint_as_float(a.w) - __uint_as_float(a.w & 0xFFFF0000u);
            float l4 = __uint_as_float(b.x) - __uint_as_float(b.x & 0xFFFF0000u);
            float l5 = __uint_as_float(b.y) - __uint_as_float(b.y & 0xFFFF0000u);
            float l6 = __uint_as_float(b.z) - __uint_as_float(b.z & 0xFFFF0000u);
            float l7 = __uint_as_float(b.w) - __uint_as_float(b.w & 0xFFFF0000u);
            uint4 lv;
            PACKBF(lv.x, l0, l1);
            PACKBF(lv.y, l2, l3);
            PACKBF(lv.z, l4, l5);
            PACKBF(lv.w, l6, l7);
            *(uint4*)(&g_Abf[m * 2048 + c8])        = hv;
            *(uint4*)(&g_Abf[m * 2048 + 1024 + c8]) = lv;
        }
        return;
    }
    // ---- rotate: Wrot = W_block @ Q, bf16 hi/lo split ----
    extern __shared__ float Qs[];
    const int b   = blockIdx.x;
    const int idx = b >> 3, oy = b & 7;
    const int proj = idx >> 3, n = idx & 7;
    const int obase = proj * 1024 + oy * 128;
    const int cbase = n * 128;
    for (int i = tid; i < 16384; i += 256) Qs[i] = g_Q[idx * 16384 + i];
    __syncthreads();
    const int c = tid & 127, half = tid >> 7;
    const float* Wp = W + (size_t)obase * 1024 + cbase;
    for (int oc = half * 64; oc < half * 64 + 64; oc += 4) {
        float acc[4] = {0.f, 0.f, 0.f, 0.f};
        #pragma unroll 4
        for (int bb = 0; bb < 128; ++bb) {
            float qv = Qs[bb * 128 + c];
            acc[0] = fmaf(Wp[(size_t)(oc + 0) * 1024 + bb], qv, acc[0]);
            acc[1] = fmaf(Wp[(size_t)(oc + 1) * 1024 + bb], qv, acc[1]);
            acc[2] = fmaf(Wp[(size_t)(oc + 2) * 1024 + bb], qv, acc[2]);
            acc[3] = fmaf(Wp[(size_t)(oc + 3) * 1024 + bb], qv, acc[3]);
        }
        #pragma unroll
        for (int u = 0; u < 4; ++u) {
            size_t o = obase + oc + u;
            float hv = __uint_as_float(__float_as_uint(acc[u]) & 0xFFFF0000u);
            g_Bbf[o * 2048 + cbase + c] =
                __ushort_as_bfloat16((unsigned short)(__float_as_uint(acc[u]) >> 16));
            g_Bbf[o * 2048 + 1024 + cbase + c] = __float2bfloat16_rn(acc[u] - hv);
        }
    }
}

// ===========================================================================
// gemm: bf16 mma.sync 3-term split. CTA 128x128, K chunks of 32, 3 stages,
// ONE barrier per chunk (wait -> sync -> compute -> issue next+2).
// ===========================================================================
#define STAGE_B 32768
#define GEMM_SMEM (3 * STAGE_B)

__global__ __launch_bounds__(256, 2)
void gemm_kernel(const float* __restrict__ bias, float* __restrict__ out) {
    extern __shared__ char smem[];
    const uint32_t sb = smem_u32(smem);
    const int tid = threadIdx.x, wid = tid >> 5, lane = tid & 31;
    const int m0 = blockIdx.y * 128, n0 = blockIdx.x * 128;
    const int wm = (wid >> 2) * 64, wn = (wid & 3) * 32;

    float c[4][4][4];
    #pragma unroll
    for (int i = 0; i < 4; ++i)
        #pragma unroll
        for (int j = 0; j < 4; ++j)
            #pragma unroll
            for (int t = 0; t < 4; ++t) c[i][j][t] = 0.f;

    const int lrow0 = tid >> 2;
    const int lkg   = tid & 3;
    const uint32_t so0 = OFFS(lrow0, lkg * 8);
    const uint32_t so1 = OFFS(lrow0 + 64, lkg * 8);
    const char* gA0 = (const char*)g_Abf + (size_t)(m0 + lrow0) * 4096 + lkg * 16;
    const char* gA1 = gA0 + (size_t)64 * 4096;
    const char* gB0 = (const char*)g_Bbf + (size_t)(n0 + lrow0) * 4096 + lkg * 16;
    const char* gB1 = gB0 + (size_t)64 * 4096;

#define ISSUE(kt) do { \
    uint32_t st = sb + ((kt) % 3) * STAGE_B; \
    size_t gk = (size_t)(kt) * 64; \
    cpa16(st + so0,         gA0 + gk); \
    cpa16(st + so1,         gA1 + gk); \
    cpa16(st +  8192 + so0, gA0 + gk + 2048); \
    cpa16(st +  8192 + so1, gA1 + gk + 2048); \
    cpa16(st + 16384 + so0, gB0 + gk); \
    cpa16(st + 16384 + so1, gB1 + gk); \
    cpa16(st + 24576 + so0, gB0 + gk + 2048); \
    cpa16(st + 24576 + so1, gB1 + gk + 2048); \
    CP_COMMIT(); \
} while (0)

    ISSUE(0);
    ISSUE(1);

    const int arow = wm + (lane & 7) + ((lane >> 3) & 1) * 8;
    const int akb  = ((lane >> 4) & 1) * 8;
    const int bnr  = wn + (lane & 7) + ((lane >> 4) & 1) * 8;
    const int bkb  = ((lane >> 3) & 1) * 8;

    for (int kt = 0; kt < 32; ++kt) {
        if (kt < 31) asm volatile("cp.async.wait_group 1;");
        else         asm volatile("cp.async.wait_group 0;");
        __syncthreads();
        const uint32_t st   = sb + (kt % 3) * STAGE_B;
        const uint32_t stAh = st, stAl = st + 8192;
        const uint32_t stBh = st + 16384, stBl = st + 24576;

        #pragma unroll
        for (int ks = 0; ks < 32; ks += 16) {
            uint32_t a[4][4], bh[2][4], bl[2][4];
            #pragma unroll
            for (int i = 0; i < 4; ++i) LDSM4(a[i], stAh + OFFS(arow + i * 16, ks + akb));
            #pragma unroll
            for (int p = 0; p < 2; ++p) {
                LDSM4(bh[p], stBh + OFFS(bnr + p * 16, ks + bkb));
                LDSM4(bl[p], stBl + OFFS(bnr + p * 16, ks + bkb));
            }
            #pragma unroll
            for (int i = 0; i < 4; ++i) {
                MMA(c[i][0], a[i], bh[0][0], bh[0][1]);
                MMA(c[i][1], a[i], bh[0][2], bh[0][3]);
                MMA(c[i][2], a[i], bh[1][0], bh[1][1]);
                MMA(c[i][3], a[i], bh[1][2], bh[1][3]);
            }
            #pragma unroll
            for (int i = 0; i < 4; ++i) {
                MMA(c[i][0], a[i], bl[0][0], bl[0][1]);
                MMA(c[i][1], a[i], bl[0][2], bl[0][3]);
                MMA(c[i][2], a[i], bl[1][0], bl[1][1]);
                MMA(c[i][3], a[i], bl[1][2], bl[1][3]);
            }
            #pragma unroll
            for (int i = 0; i < 4; ++i) LDSM4(a[i], stAl + OFFS(arow + i * 16, ks + akb));
            #pragma unroll
            for (int i = 0; i < 4; ++i) {
                MMA(c[i][0], a[i], bh[0][0], bh[0][1]);
                MMA(c[i][1], a[i], bh[0][2], bh[0][3]);
                MMA(c[i][2], a[i], bh[1][0], bh[1][1]);
                MMA(c[i][3], a[i], bh[1][2], bh[1][3]);
            }
        }
        if (kt + 2 < 32) ISSUE(kt + 2);
    }

    float2 bj[4];
    #pragma unroll
    for (int j = 0; j < 4; ++j)
        bj[j] = *(const float2*)(bias + n0 + wn + j * 8 + (lane & 3) * 2);

    #pragma unroll
    for (int i = 0; i < 4; ++i) {
        const int r = m0 + wm + i * 16 + (lane >> 2);
        #pragma unroll
        for (int j = 0; j < 4; ++j) {
            const int col = n0 + wn + j * 8 + (lane & 3) * 2;
            float2 v0 = {c[i][j][0] + bj[j].x, c[i][j][1] + bj[j].y};
            float2 v1 = {c[i][j][2] + bj[j].x, c[i][j][3] + bj[j].y};
            *(float2*)(out + (size_t)r * 3072 + col)       = v0;
            *(float2*)(out + (size_t)(r + 8) * 3072 + col) = v1;
        }
    }
}

// ---------------------------------------------------------------------------
extern "C" void kernel_launch(void* const* d_in, const int* in_sizes, int n_in,
                              void* d_out, int out_size) {
    const float* W    = (const float*)d_in[0];
    const float* bias = (const float*)d_in[1];
    const float* x    = (const float*)d_in[2];
    const float* qR   = (const float*)d_in[3];
    const float* kR   = (const float*)d_in[4];
    const float* vR   = (const float*)d_in[5];
    float* out = (float*)d_out;

    cudaFuncSetAttribute(work_kernel, cudaFuncAttributeMaxDynamicSharedMemorySize, 65536);
    cudaFuncSetAttribute(gemm_kernel, cudaFuncAttributeMaxDynamicSharedMemorySize, GEMM_SMEM);

    cayley_kernel<<<24, 512>>>(qR, kR, vR);
    work_kernel<<<192 + CONV_BLKS, 256, 65536>>>(W, x);
    gemm_kernel<<<dim3(24, 256), 256, GEMM_SMEM>>>(bias, out);
}

// round 10
// speedup vs baseline: 3.1869x; 1.0205x over previous
#include <cuda_runtime.h>
#include <cuda_bf16.h>
#include <cstdint>

typedef unsigned long long ull;
#define EPSF 1e-6f

__device__ float          g_Q[24 * 128 * 128];
__device__ __nv_bfloat16  g_Abf[(size_t)32768 * 2048];  // x split: hi cols 0..1023, lo 1024..2047
__device__ __nv_bfloat16  g_Bbf[(size_t)3072 * 2048];   // rotated W split

__device__ __forceinline__ uint32_t smem_u32(const void* p) {
    uint32_t a;
    asm("{ .reg .u64 t; cvta.to.shared.u64 t, %1; cvt.u32.u64 %0, t; }" : "=r"(a) : "l"(p));
    return a;
}
__device__ __forceinline__ void cpa16(uint32_t s, const void* g) {
    asm volatile("cp.async.cg.shared.global [%0], [%1], 16;" :: "r"(s), "l"(g));
}
#define CP_COMMIT() asm volatile("cp.async.commit_group;")

// swizzled byte offset of element (row, k) in a [128][32] bf16 tile, 64B rows.
#define OFFS(row, k) ((uint32_t)((row) * 64 + ((((k) >> 3) ^ (((row) >> 1) & 3)) << 4)))

#define LDSM4(r, ad) \
    asm volatile("ldmatrix.sync.aligned.m8n8.x4.shared.b16 {%0,%1,%2,%3}, [%4];" \
        : "=r"((r)[0]), "=r"((r)[1]), "=r"((r)[2]), "=r"((r)[3]) : "r"(ad))

#define MMA(cc, A, b0, b1) \
    asm volatile("mma.sync.aligned.m16n8k16.row.col.f32.bf16.bf16.f32 " \
        "{%0,%1,%2,%3},{%4,%5,%6,%7},{%8,%9},{%0,%1,%2,%3};" \
        : "+f"((cc)[0]), "+f"((cc)[1]), "+f"((cc)[2]), "+f"((cc)[3]) \
        : "r"((A)[0]), "r"((A)[1]), "r"((A)[2]), "r"((A)[3]), "r"(b0), "r"(b1))

#define PACKBF(d, flo, fhi) \
    asm("cvt.rn.bf16x2.f32 %0, %1, %2;" : "=r"(d) : "f"(fhi), "f"(flo))

// static-index register access via dense switch (BRX table, no local spill)
__device__ __forceinline__ void setreg(float* a, int i, float v) {
    switch (i) {
#define CS(J) case J: a[J] = v; break;
        CS(0) CS(1) CS(2) CS(3) CS(4) CS(5) CS(6) CS(7)
        CS(8) CS(9) CS(10) CS(11) CS(12) CS(13) CS(14) CS(15)
        CS(16) CS(17) CS(18) CS(19) CS(20) CS(21) CS(22) CS(23)
        CS(24) CS(25) CS(26) CS(27) CS(28) CS(29) CS(30) CS(31)
#undef CS
    }
}
__device__ __forceinline__ float getreg(const float* a, int i) {
    float v = 0.f;
    switch (i) {
#define CG(J) case J: v = a[J]; break;
        CG(0) CG(1) CG(2) CG(3) CG(4) CG(5) CG(6) CG(7)
        CG(8) CG(9) CG(10) CG(11) CG(12) CG(13) CG(14) CG(15)
        CG(16) CG(17) CG(18) CG(19) CG(20) CG(21) CG(22) CG(23)
        CG(24) CG(25) CG(26) CG(27) CG(28) CG(29) CG(30) CG(31)
#undef CG
    }
    return v;
}

// ===========================================================================
// cayley: Q = (2+eps)*inv(I+S+epsI) - I. Register GJ, lean inner loop:
// 8x LDS.128 + 32 FFMA per step; special-element fixups via switch.
// ===========================================================================
__global__ __launch_bounds__(512)
void cayley_kernel(const float* __restrict__ qR, const float* __restrict__ kR,
                   const float* __restrict__ vR) {
    const int tid = threadIdx.x;
    __shared__ float rowb[2][132];   // 528B row stride (16B aligned)
    __shared__ float colb[2][128];
    const int idx  = blockIdx.x;
    const int proj = idx >> 3, n = idx & 7;
    const float* src = (proj == 0 ? qR : (proj == 1 ? kR : vR)) + n * 16384;
    const int r = tid & 127, q = tid >> 7, c0 = q * 32;

    float regs[32];
    #pragma unroll
    for (int j = 0; j < 32; ++j) {
        int c = c0 + j;
        float v = 0.5f * (src[r * 128 + c] - src[c * 128 + r]);
        if (c == r) v += 1.0f + EPSF;
        regs[j] = v;
    }
    if (r == 0) {
        #pragma unroll
        for (int j = 0; j < 32; ++j) rowb[0][c0 + j] = regs[j];
    }
    if (q == 0) colb[0][r] = regs[0];

    for (int k = 0; k < 128; ++k) {
        const int b = k & 1, nb = b ^ 1;
        __syncthreads();
        const float pivinv = 1.0f / rowb[b][k];
        const float f      = colb[b][r];
        const bool  own    = (q == (k >> 5));     // this thread owns column k
        if (r == k) {
            #pragma unroll
            for (int j = 0; j < 32; ++j) regs[j] *= pivinv;
            if (own) setreg(regs, k & 31, pivinv);
        } else {
            const float t = f * pivinv;
            const float4* rp = (const float4*)&rowb[b][c0];
            #pragma unroll
            for (int v4 = 0; v4 < 8; ++v4) {
                float4 rv = rp[v4];
                regs[4 * v4 + 0] = fmaf(-t, rv.x, regs[4 * v4 + 0]);
                regs[4 * v4 + 1] = fmaf(-t, rv.y, regs[4 * v4 + 1]);
                regs[4 * v4 + 2] = fmaf(-t, rv.z, regs[4 * v4 + 2]);
                regs[4 * v4 + 3] = fmaf(-t, rv.w, regs[4 * v4 + 3]);
            }
            if (own) setreg(regs, k & 31, -t);
        }
        if (k < 127) {
            const int k1 = k + 1;
            if (r == k1) {
                float4* wp = (float4*)&rowb[nb][c0];
                #pragma unroll
                for (int v4 = 0; v4 < 8; ++v4)
                    wp[v4] = make_float4(regs[4 * v4 + 0], regs[4 * v4 + 1],
                                         regs[4 * v4 + 2], regs[4 * v4 + 3]);
            }
            if (q == (k1 >> 5)) colb[nb][r] = getreg(regs, k1 & 31);
        }
    }
    float* dst = g_Q + idx * 16384 + r * 128 + c0;
    const float s = 2.0f + EPSF;
    #pragma unroll
    for (int j = 0; j < 32; ++j) {
        float v = s * regs[j];
        if (c0 + j == r) v -= 1.0f;
        dst[j] = v;
    }
}

// ===========================================================================
// work: blocks 0-191 rotate (needs g_Q), blocks 192+ convert x.
// ===========================================================================
#define CONV_BLKS 896
__global__ __launch_bounds__(256)
void work_kernel(const float* __restrict__ W, const float* __restrict__ x) {
    const int tid = threadIdx.x;
    if (blockIdx.x >= 192) {
        const uint4* xv = (const uint4*)x;
        const size_t stride = (size_t)CONV_BLKS * 256;
        for (size_t u = (size_t)(blockIdx.x - 192) * 256 + tid;
             u < (size_t)32768 * 128; u += stride) {
            size_t m  = u >> 7;
            int    c8 = (int)(u & 127) * 8;
            uint4 a = xv[2 * u];
            uint4 b = xv[2 * u + 1];
            uint4 hv;
            hv.x = __byte_perm(a.x, a.y, 0x7632);
            hv.y = __byte_perm(a.z, a.w, 0x7632);
            hv.z = __byte_perm(b.x, b.y, 0x7632);
            hv.w = __byte_perm(b.z, b.w, 0x7632);
            float l0 = __uint_as_float(a.x) - __uint_as_float(a.x & 0xFFFF0000u);
            float l1 = __uint_as_float(a.y) - __uint_as_float(a.y & 0xFFFF0000u);
            float l2 = __uint_as_float(a.z) - __uint_as_float(a.z & 0xFFFF0000u);
            float l3 = __uint_as_float(a.w) - __uint_as_float(a.w & 0xFFFF0000u);
            float l4 = __uint_as_float(b.x) - __uint_as_float(b.x & 0xFFFF0000u);
            float l5 = __uint_as_float(b.y) - __uint_as_float(b.y & 0xFFFF0000u);
            float l6 = __uint_as_float(b.z) - __uint_as_float(b.z & 0xFFFF0000u);
            float l7 = __uint_as_float(b.w) - __uint_as_float(b.w & 0xFFFF0000u);
            uint4 lv;
            PACKBF(lv.x, l0, l1);
            PACKBF(lv.y, l2, l3);
            PACKBF(lv.z, l4, l5);
            PACKBF(lv.w, l6, l7);
            *(uint4*)(&g_Abf[m * 2048 + c8])        = hv;
            *(uint4*)(&g_Abf[m * 2048 + 1024 + c8]) = lv;
        }
        return;
    }
    extern __shared__ float Qs[];
    const int b   = blockIdx.x;
    const int idx = b >> 3, oy = b & 7;
    const int proj = idx >> 3, n = idx & 7;
    const int obase = proj * 1024 + oy * 128;
    const int cbase = n * 128;
    for (int i = tid; i < 16384; i += 256) Qs[i] = g_Q[idx * 16384 + i];
    __syncthreads();
    const int c = tid & 127, half = tid >> 7;
    const float* Wp = W + (size_t)obase * 1024 + cbase;
    for (int oc = half * 64; oc < half * 64 + 64; oc += 4) {
        float acc[4] = {0.f, 0.f, 0.f, 0.f};
        #pragma unroll 4
        for (int bb = 0; bb < 128; ++bb) {
            float qv = Qs[bb * 128 + c];
            acc[0] = fmaf(Wp[(size_t)(oc + 0) * 1024 + bb], qv, acc[0]);
            acc[1] = fmaf(Wp[(size_t)(oc + 1) * 1024 + bb], qv, acc[1]);
            acc[2] = fmaf(Wp[(size_t)(oc + 2) * 1024 + bb], qv, acc[2]);
            acc[3] = fmaf(Wp[(size_t)(oc + 3) * 1024 + bb], qv, acc[3]);
        }
        #pragma unroll
        for (int u = 0; u < 4; ++u) {
            size_t o = obase + oc + u;
            float hv = __uint_as_float(__float_as_uint(acc[u]) & 0xFFFF0000u);
            g_Bbf[o * 2048 + cbase + c] =
                __ushort_as_bfloat16((unsigned short)(__float_as_uint(acc[u]) >> 16));
            g_Bbf[o * 2048 + 1024 + cbase + c] = __float2bfloat16_rn(acc[u] - hv);
        }
    }
}

// ===========================================================================
// gemm: bf16 mma.sync 3-term split. CTA 128x128, K chunks of 32, 3 stages,
// one barrier per chunk.
// ===========================================================================
#define STAGE_B 32768
#define GEMM_SMEM (3 * STAGE_B)

__global__ __launch_bounds__(256, 2)
void gemm_kernel(const float* __restrict__ bias, float* __restrict__ out) {
    extern __shared__ char smem[];
    const uint32_t sb = smem_u32(smem);
    const int tid = threadIdx.x, wid = tid >> 5, lane = tid & 31;
    const int m0 = blockIdx.y * 128, n0 = blockIdx.x * 128;
    const int wm = (wid >> 2) * 64, wn = (wid & 3) * 32;

    float c[4][4][4];
    #pragma unroll
    for (int i = 0; i < 4; ++i)
        #pragma unroll
        for (int j = 0; j < 4; ++j)
            #pragma unroll
            for (int t = 0; t < 4; ++t) c[i][j][t] = 0.f;

    const int lrow0 = tid >> 2;
    const int lkg   = tid & 3;
    const uint32_t so0 = OFFS(lrow0, lkg * 8);
    const uint32_t so1 = OFFS(lrow0 + 64, lkg * 8);
    const char* gA0 = (const char*)g_Abf + (size_t)(m0 + lrow0) * 4096 + lkg * 16;
    const char* gA1 = gA0 + (size_t)64 * 4096;
    const char* gB0 = (const char*)g_Bbf + (size_t)(n0 + lrow0) * 4096 + lkg * 16;
    const char* gB1 = gB0 + (size_t)64 * 4096;

#define ISSUE(kt) do { \
    uint32_t st = sb + ((kt) % 3) * STAGE_B; \
    size_t gk = (size_t)(kt) * 64; \
    cpa16(st + so0,         gA0 + gk); \
    cpa16(st + so1,         gA1 + gk); \
    cpa16(st +  8192 + so0, gA0 + gk + 2048); \
    cpa16(st +  8192 + so1, gA1 + gk + 2048); \
    cpa16(st + 16384 + so0, gB0 + gk); \
    cpa16(st + 16384 + so1, gB1 + gk); \
    cpa16(st + 24576 + so0, gB0 + gk + 2048); \
    cpa16(st + 24576 + so1, gB1 + gk + 2048); \
    CP_COMMIT(); \
} while (0)

    ISSUE(0);
    ISSUE(1);

    const int arow = wm + (lane & 7) + ((lane >> 3) & 1) * 8;
    const int akb  = ((lane >> 4) & 1) * 8;
    const int bnr  = wn + (lane & 7) + ((lane >> 4) & 1) * 8;
    const int bkb  = ((lane >> 3) & 1) * 8;

    for (int kt = 0; kt < 32; ++kt) {
        if (kt < 31) asm volatile("cp.async.wait_group 1;");
        else         asm volatile("cp.async.wait_group 0;");
        __syncthreads();
        const uint32_t st   = sb + (kt % 3) * STAGE_B;
        const uint32_t stAh = st, stAl = st + 8192;
        const uint32_t stBh = st + 16384, stBl = st + 24576;

        #pragma unroll
        for (int ks = 0; ks < 32; ks += 16) {
            uint32_t a[4][4], bh[2][4], bl[2][4];
            #pragma unroll
            for (int i = 0; i < 4; ++i) LDSM4(a[i], stAh + OFFS(arow + i * 16, ks + akb));
            #pragma unroll
            for (int p = 0; p < 2; ++p) {
                LDSM4(bh[p], stBh + OFFS(bnr + p * 16, ks + bkb));
                LDSM4(bl[p], stBl + OFFS(bnr + p * 16, ks + bkb));
            }
            #pragma unroll
            for (int i = 0; i < 4; ++i) {
                MMA(c[i][0], a[i], bh[0][0], bh[0][1]);
                MMA(c[i][1], a[i], bh[0][2], bh[0][3]);
                MMA(c[i][2], a[i], bh[1][0], bh[1][1]);
                MMA(c[i][3], a[i], bh[1][2], bh[1][3]);
            }
            #pragma unroll
            for (int i = 0; i < 4; ++i) {
                MMA(c[i][0], a[i], bl[0][0], bl[0][1]);
                MMA(c[i][1], a[i], bl[0][2], bl[0][3]);
                MMA(c[i][2], a[i], bl[1][0], bl[1][1]);
                MMA(c[i][3], a[i], bl[1][2], bl[1][3]);
            }
            #pragma unroll
            for (int i = 0; i < 4; ++i) LDSM4(a[i], stAl + OFFS(arow + i * 16, ks + akb));
            #pragma unroll
            for (int i = 0; i < 4; ++i) {
                MMA(c[i][0], a[i], bh[0][0], bh[0][1]);
                MMA(c[i][1], a[i], bh[0][2], bh[0][3]);
                MMA(c[i][2], a[i], bh[1][0], bh[1][1]);
                MMA(c[i][3], a[i], bh[1][2], bh[1][3]);
            }
        }
        if (kt + 2 < 32) ISSUE(kt + 2);
    }

    float2 bj[4];
    #pragma unroll
    for (int j = 0; j < 4; ++j)
        bj[j] = *(const float2*)(bias + n0 + wn + j * 8 + (lane & 3) * 2);

    #pragma unroll
    for (int i = 0; i < 4; ++i) {
        const int r = m0 + wm + i * 16 + (lane >> 2);
        #pragma unroll
        for (int j = 0; j < 4; ++j) {
            const int col = n0 + wn + j * 8 + (lane & 3) * 2;
            float2 v0 = {c[i][j][0] + bj[j].x, c[i][j][1] + bj[j].y};
            float2 v1 = {c[i][j][2] + bj[j].x, c[i][j][3] + bj[j].y};
            *(float2*)(out + (size_t)r * 3072 + col)       = v0;
            *(float2*)(out + (size_t)(r + 8) * 3072 + col) = v1;
        }
    }
}

// ---------------------------------------------------------------------------
extern "C" void kernel_launch(void* const* d_in, const int* in_sizes, int n_in,
                              void* d_out, int out_size) {
    const float* W    = (const float*)d_in[0];
    const float* bias = (const float*)d_in[1];
    const float* x    = (const float*)d_in[2];
    const float* qR   = (const float*)d_in[3];
    const float* kR   = (const float*)d_in[4];
    const float* vR   = (const float*)d_in[5];
    float* out = (float*)d_out;

    cudaFuncSetAttribute(work_kernel, cudaFuncAttributeMaxDynamicSharedMemorySize, 65536);
    cudaFuncSetAttribute(gemm_kernel, cudaFuncAttributeMaxDynamicSharedMemorySize, GEMM_SMEM);

    cayley_kernel<<<24, 512>>>(qR, kR, vR);
    work_kernel<<<192 + CONV_BLKS, 256, 65536>>>(W, x);
    gemm_kernel<<<dim3(24, 256), 256, GEMM_SMEM>>>(bias, out);
}

// round 11
// speedup vs baseline: 3.2250x; 1.0120x over previous
#include <cuda_runtime.h>
#include <cuda_bf16.h>
#include <cstdint>

typedef unsigned long long ull;
#define EPSF 1e-6f

__device__ float          g_Q[24 * 128 * 128];
__device__ __nv_bfloat16  g_Abf[(size_t)32768 * 2048];  // x split: hi cols 0..1023, lo 1024..2047
__device__ __nv_bfloat16  g_Bbf[(size_t)3072 * 2048];   // rotated W split

__device__ __forceinline__ uint32_t smem_u32(const void* p) {
    uint32_t a;
    asm("{ .reg .u64 t; cvta.to.shared.u64 t, %1; cvt.u32.u64 %0, t; }" : "=r"(a) : "l"(p));
    return a;
}
__device__ __forceinline__ void cpa16(uint32_t s, const void* g) {
    asm volatile("cp.async.cg.shared.global [%0], [%1], 16;" :: "r"(s), "l"(g));
}
#define CP_COMMIT() asm volatile("cp.async.commit_group;")

// swizzled byte offset of element (row, k) in a [128][32] bf16 tile, 64B rows.
#define OFFS(row, k) ((uint32_t)((row) * 64 + ((((k) >> 3) ^ (((row) >> 1) & 3)) << 4)))

#define LDSM4(r, ad) \
    asm volatile("ldmatrix.sync.aligned.m8n8.x4.shared.b16 {%0,%1,%2,%3}, [%4];" \
        : "=r"((r)[0]), "=r"((r)[1]), "=r"((r)[2]), "=r"((r)[3]) : "r"(ad))

#define MMA(cc, A, b0, b1) \
    asm volatile("mma.sync.aligned.m16n8k16.row.col.f32.bf16.bf16.f32 " \
        "{%0,%1,%2,%3},{%4,%5,%6,%7},{%8,%9},{%0,%1,%2,%3};" \
        : "+f"((cc)[0]), "+f"((cc)[1]), "+f"((cc)[2]), "+f"((cc)[3]) \
        : "r"((A)[0]), "r"((A)[1]), "r"((A)[2]), "r"((A)[3]), "r"(b0), "r"(b1))

#define PACKBF(d, flo, fhi) \
    asm("cvt.rn.bf16x2.f32 %0, %1, %2;" : "=r"(d) : "f"(fhi), "f"(flo))

// static-index register access via dense switch (no local spill)
__device__ __forceinline__ void setreg(float* a, int i, float v) {
    switch (i) {
#define CS(J) case J: a[J] = v; break;
        CS(0) CS(1) CS(2) CS(3) CS(4) CS(5) CS(6) CS(7)
        CS(8) CS(9) CS(10) CS(11) CS(12) CS(13) CS(14) CS(15)
        CS(16) CS(17) CS(18) CS(19) CS(20) CS(21) CS(22) CS(23)
        CS(24) CS(25) CS(26) CS(27) CS(28) CS(29) CS(30) CS(31)
#undef CS
    }
}
__device__ __forceinline__ float getreg(const float* a, int i) {
    float v = 0.f;
    switch (i) {
#define CG(J) case J: v = a[J]; break;
        CG(0) CG(1) CG(2) CG(3) CG(4) CG(5) CG(6) CG(7)
        CG(8) CG(9) CG(10) CG(11) CG(12) CG(13) CG(14) CG(15)
        CG(16) CG(17) CG(18) CG(19) CG(20) CG(21) CG(22) CG(23)
        CG(24) CG(25) CG(26) CG(27) CG(28) CG(29) CG(30) CG(31)
#undef CG
    }
    return v;
}

// ===========================================================================
// prep: blocks 0-23 cayley (register GJ); blocks 24+ convert x -> bf16 split.
// Convert is independent of cayley and fills the idle SMs under it.
// ===========================================================================
__global__ __launch_bounds__(512)
void prep_kernel(const float* __restrict__ qR, const float* __restrict__ kR,
                 const float* __restrict__ vR, const float* __restrict__ x) {
    const int tid = threadIdx.x;
    if (blockIdx.x >= 24) {
        const uint4* xv = (const uint4*)x;
        const size_t stride = (size_t)1024 * 512;
        for (size_t u = (size_t)(blockIdx.x - 24) * 512 + tid;
             u < (size_t)32768 * 128; u += stride) {
            size_t m  = u >> 7;
            int    c8 = (int)(u & 127) * 8;
            uint4 a = xv[2 * u];
            uint4 b = xv[2 * u + 1];
            uint4 hv;
            hv.x = __byte_perm(a.x, a.y, 0x7632);
            hv.y = __byte_perm(a.z, a.w, 0x7632);
            hv.z = __byte_perm(b.x, b.y, 0x7632);
            hv.w = __byte_perm(b.z, b.w, 0x7632);
            float l0 = __uint_as_float(a.x) - __uint_as_float(a.x & 0xFFFF0000u);
            float l1 = __uint_as_float(a.y) - __uint_as_float(a.y & 0xFFFF0000u);
            float l2 = __uint_as_float(a.z) - __uint_as_float(a.z & 0xFFFF0000u);
            float l3 = __uint_as_float(a.w) - __uint_as_float(a.w & 0xFFFF0000u);
            float l4 = __uint_as_float(b.x) - __uint_as_float(b.x & 0xFFFF0000u);
            float l5 = __uint_as_float(b.y) - __uint_as_float(b.y & 0xFFFF0000u);
            float l6 = __uint_as_float(b.z) - __uint_as_float(b.z & 0xFFFF0000u);
            float l7 = __uint_as_float(b.w) - __uint_as_float(b.w & 0xFFFF0000u);
            uint4 lv;
            PACKBF(lv.x, l0, l1);
            PACKBF(lv.y, l2, l3);
            PACKBF(lv.z, l4, l5);
            PACKBF(lv.w, l6, l7);
            *(uint4*)(&g_Abf[m * 2048 + c8])        = hv;
            *(uint4*)(&g_Abf[m * 2048 + 1024 + c8]) = lv;
        }
        return;
    }
    // ---- cayley: Q = (2+eps)*inv(I+S+epsI) - I ----
    __shared__ float rowb[2][132];
    __shared__ float colb[2][128];
    const int idx  = blockIdx.x;
    const int proj = idx >> 3, n = idx & 7;
    const float* src = (proj == 0 ? qR : (proj == 1 ? kR : vR)) + n * 16384;
    const int r = tid & 127, q = tid >> 7, c0 = q * 32;

    float regs[32];
    #pragma unroll
    for (int j = 0; j < 32; ++j) {
        int c = c0 + j;
        float v = 0.5f * (src[r * 128 + c] - src[c * 128 + r]);
        if (c == r) v += 1.0f + EPSF;
        regs[j] = v;
    }
    if (r == 0) {
        #pragma unroll
        for (int j = 0; j < 32; ++j) rowb[0][c0 + j] = regs[j];
    }
    if (q == 0) colb[0][r] = regs[0];

    for (int k = 0; k < 128; ++k) {
        const int b = k & 1, nb = b ^ 1;
        __syncthreads();
        const float pivinv = 1.0f / rowb[b][k];
        const float f      = colb[b][r];
        const bool  own    = (q == (k >> 5));
        if (r == k) {
            #pragma unroll
            for (int j = 0; j < 32; ++j) regs[j] *= pivinv;
            if (own) setreg(regs, k & 31, pivinv);
        } else {
            const float t = f * pivinv;
            const float4* rp = (const float4*)&rowb[b][c0];
            #pragma unroll
            for (int v4 = 0; v4 < 8; ++v4) {
                float4 rv = rp[v4];
                regs[4 * v4 + 0] = fmaf(-t, rv.x, regs[4 * v4 + 0]);
                regs[4 * v4 + 1] = fmaf(-t, rv.y, regs[4 * v4 + 1]);
                regs[4 * v4 + 2] = fmaf(-t, rv.z, regs[4 * v4 + 2]);
                regs[4 * v4 + 3] = fmaf(-t, rv.w, regs[4 * v4 + 3]);
            }
            if (own) setreg(regs, k & 31, -t);
        }
        if (k < 127) {
            const int k1 = k + 1;
            if (r == k1) {
                float4* wp = (float4*)&rowb[nb][c0];
                #pragma unroll
                for (int v4 = 0; v4 < 8; ++v4)
                    wp[v4] = make_float4(regs[4 * v4 + 0], regs[4 * v4 + 1],
                                         regs[4 * v4 + 2], regs[4 * v4 + 3]);
            }
            if (q == (k1 >> 5)) colb[nb][r] = getreg(regs, k1 & 31);
        }
    }
    float* dst = g_Q + idx * 16384 + r * 128 + c0;
    const float s = 2.0f + EPSF;
    #pragma unroll
    for (int j = 0; j < 32; ++j) {
        float v = s * regs[j];
        if (c0 + j == r) v -= 1.0f;
        dst[j] = v;
    }
}

// ===========================================================================
// rotate: Wrot = W_block @ Q, bf16 hi/lo split. 192 CTAs.
// ===========================================================================
__global__ __launch_bounds__(256)
void rotate_kernel(const float* __restrict__ W) {
    extern __shared__ float Qs[];
    const int tid = threadIdx.x;
    const int b   = blockIdx.x;
    const int idx = b >> 3, oy = b & 7;
    const int proj = idx >> 3, n = idx & 7;
    const int obase = proj * 1024 + oy * 128;
    const int cbase = n * 128;
    for (int i = tid; i < 16384; i += 256) Qs[i] = g_Q[idx * 16384 + i];
    __syncthreads();
    const int c = tid & 127, half = tid >> 7;
    const float* Wp = W + (size_t)obase * 1024 + cbase;
    for (int oc = half * 64; oc < half * 64 + 64; oc += 4) {
        float acc[4] = {0.f, 0.f, 0.f, 0.f};
        #pragma unroll 4
        for (int bb = 0; bb < 128; ++bb) {
            float qv = Qs[bb * 128 + c];
            acc[0] = fmaf(Wp[(size_t)(oc + 0) * 1024 + bb], qv, acc[0]);
            acc[1] = fmaf(Wp[(size_t)(oc + 1) * 1024 + bb], qv, acc[1]);
            acc[2] = fmaf(Wp[(size_t)(oc + 2) * 1024 + bb], qv, acc[2]);
            acc[3] = fmaf(Wp[(size_t)(oc + 3) * 1024 + bb], qv, acc[3]);
        }
        #pragma unroll
        for (int u = 0; u < 4; ++u) {
            size_t o = obase + oc + u;
            float hv = __uint_as_float(__float_as_uint(acc[u]) & 0xFFFF0000u);
            g_Bbf[o * 2048 + cbase + c] =
                __ushort_as_bfloat16((unsigned short)(__float_as_uint(acc[u]) >> 16));
            g_Bbf[o * 2048 + 1024 + cbase + c] = __float2bfloat16_rn(acc[u] - hv);
        }
    }
}

// ===========================================================================
// gemm: bf16 mma.sync 3-term split. CTA 128x128, K chunks of 32, 3 stages,
// one barrier per chunk; next-chunk cp.async issued mid-chunk.
// ===========================================================================
#define STAGE_B 32768
#define GEMM_SMEM (3 * STAGE_B)

__global__ __launch_bounds__(256, 2)
void gemm_kernel(const float* __restrict__ bias, float* __restrict__ out) {
    extern __shared__ char smem[];
    const uint32_t sb = smem_u32(smem);
    const int tid = threadIdx.x, wid = tid >> 5, lane = tid & 31;
    const int m0 = blockIdx.y * 128, n0 = blockIdx.x * 128;
    const int wm = (wid >> 2) * 64, wn = (wid & 3) * 32;

    float c[4][4][4];
    #pragma unroll
    for (int i = 0; i < 4; ++i)
        #pragma unroll
        for (int j = 0; j < 4; ++j)
            #pragma unroll
            for (int t = 0; t < 4; ++t) c[i][j][t] = 0.f;

    const int lrow0 = tid >> 2;
    const int lkg   = tid & 3;
    const uint32_t so0 = OFFS(lrow0, lkg * 8);
    const uint32_t so1 = OFFS(lrow0 + 64, lkg * 8);
    const char* gA0 = (const char*)g_Abf + (size_t)(m0 + lrow0) * 4096 + lkg * 16;
    const char* gA1 = gA0 + (size_t)64 * 4096;
    const char* gB0 = (const char*)g_Bbf + (size_t)(n0 + lrow0) * 4096 + lkg * 16;
    const char* gB1 = gB0 + (size_t)64 * 4096;

#define ISSUE(kt) do { \
    uint32_t st = sb + ((kt) % 3) * STAGE_B; \
    size_t gk = (size_t)(kt) * 64; \
    cpa16(st + so0,         gA0 + gk); \
    cpa16(st + so1,         gA1 + gk); \
    cpa16(st +  8192 + so0, gA0 + gk + 2048); \
    cpa16(st +  8192 + so1, gA1 + gk + 2048); \
    cpa16(st + 16384 + so0, gB0 + gk); \
    cpa16(st + 16384 + so1, gB1 + gk); \
    cpa16(st + 24576 + so0, gB0 + gk + 2048); \
    cpa16(st + 24576 + so1, gB1 + gk + 2048); \
    CP_COMMIT(); \
} while (0)

#define KS_BODY(ks) do { \
    uint32_t a[4][4], bh[2][4], bl[2][4]; \
    _Pragma("unroll") \
    for (int i = 0; i < 4; ++i) LDSM4(a[i], stAh + OFFS(arow + i * 16, (ks) + akb)); \
    _Pragma("unroll") \
    for (int p = 0; p < 2; ++p) { \
        LDSM4(bh[p], stBh + OFFS(bnr + p * 16, (ks) + bkb)); \
        LDSM4(bl[p], stBl + OFFS(bnr + p * 16, (ks) + bkb)); \
    } \
    _Pragma("unroll") \
    for (int i = 0; i < 4; ++i) { \
        MMA(c[i][0], a[i], bh[0][0], bh[0][1]); \
        MMA(c[i][1], a[i], bh[0][2], bh[0][3]); \
        MMA(c[i][2], a[i], bh[1][0], bh[1][1]); \
        MMA(c[i][3], a[i], bh[1][2], bh[1][3]); \
    } \
    _Pragma("unroll") \
    for (int i = 0; i < 4; ++i) { \
        MMA(c[i][0], a[i], bl[0][0], bl[0][1]); \
        MMA(c[i][1], a[i], bl[0][2], bl[0][3]); \
        MMA(c[i][2], a[i], bl[1][0], bl[1][1]); \
        MMA(c[i][3], a[i], bl[1][2], bl[1][3]); \
    } \
    _Pragma("unroll") \
    for (int i = 0; i < 4; ++i) LDSM4(a[i], stAl + OFFS(arow + i * 16, (ks) + akb)); \
    _Pragma("unroll") \
    for (int i = 0; i < 4; ++i) { \
        MMA(c[i][0], a[i], bh[0][0], bh[0][1]); \
        MMA(c[i][1], a[i], bh[0][2], bh[0][3]); \
        MMA(c[i][2], a[i], bh[1][0], bh[1][1]); \
        MMA(c[i][3], a[i], bh[1][2], bh[1][3]); \
    } \
} while (0)

    ISSUE(0);
    ISSUE(1);

    const int arow = wm + (lane & 7) + ((lane >> 3) & 1) * 8;
    const int akb  = ((lane >> 4) & 1) * 8;
    const int bnr  = wn + (lane & 7) + ((lane >> 4) & 1) * 8;
    const int bkb  = ((lane >> 3) & 1) * 8;

    for (int kt = 0; kt < 32; ++kt) {
        if (kt < 31) asm volatile("cp.async.wait_group 1;");
        else         asm volatile("cp.async.wait_group 0;");
        __syncthreads();
        const uint32_t st   = sb + (kt % 3) * STAGE_B;
        const uint32_t stAh = st, stAl = st + 8192;
        const uint32_t stBh = st + 16384, stBl = st + 24576;

        KS_BODY(0);
        if (kt + 2 < 32) ISSUE(kt + 2);   // after barrier: slot (kt-1)%3 free
        KS_BODY(16);
    }

    float2 bj[4];
    #pragma unroll
    for (int j = 0; j < 4; ++j)
        bj[j] = *(const float2*)(bias + n0 + wn + j * 8 + (lane & 3) * 2);

    #pragma unroll
    for (int i = 0; i < 4; ++i) {
        const int r = m0 + wm + i * 16 + (lane >> 2);
        #pragma unroll
        for (int j = 0; j < 4; ++j) {
            const int col = n0 + wn + j * 8 + (lane & 3) * 2;
            float2 v0 = {c[i][j][0] + bj[j].x, c[i][j][1] + bj[j].y};
            float2 v1 = {c[i][j][2] + bj[j].x, c[i][j][3] + bj[j].y};
            *(float2*)(out + (size_t)r * 3072 + col)       = v0;
            *(float2*)(out + (size_t)(r + 8) * 3072 + col) = v1;
        }
    }
}

// ---------------------------------------------------------------------------
extern "C" void kernel_launch(void* const* d_in, const int* in_sizes, int n_in,
                              void* d_out, int out_size) {
    const float* W    = (const float*)d_in[0];
    const float* bias = (const float*)d_in[1];
    const float* x    = (const float*)d_in[2];
    const float* qR   = (const float*)d_in[3];
    const float* kR   = (const float*)d_in[4];
    const float* vR   = (const float*)d_in[5];
    float* out = (float*)d_out;

    cudaFuncSetAttribute(rotate_kernel, cudaFuncAttributeMaxDynamicSharedMemorySize, 65536);
    cudaFuncSetAttribute(gemm_kernel,   cudaFuncAttributeMaxDynamicSharedMemorySize, GEMM_SMEM);

    prep_kernel<<<24 + 1024, 512>>>(qR, kR, vR, x);
    rotate_kernel<<<192, 256, 65536>>>(W);
    gemm_kernel<<<dim3(24, 256), 256, GEMM_SMEM>>>(bias, out);
}

// round 12
// speedup vs baseline: 4.2882x; 1.3297x over previous
#include <cuda_runtime.h>
#include <cuda_fp16.h>
#include <cstdint>

typedef unsigned long long ull;
#define EPSF 1e-6f

__device__ float   g_Q[24 * 128 * 128];
__device__ __half  g_Ah[(size_t)32768 * 2048];  // x split fp16: hi cols 0..1023, lo 1024..2047
__device__ __half  g_Bh[(size_t)3072 * 1024];   // rotated W, single fp16

__device__ __forceinline__ uint32_t smem_u32(const void* p) {
    uint32_t a;
    asm("{ .reg .u64 t; cvta.to.shared.u64 t, %1; cvt.u32.u64 %0, t; }" : "=r"(a) : "l"(p));
    return a;
}
__device__ __forceinline__ void cpa16(uint32_t s, const void* g) {
    asm volatile("cp.async.cg.shared.global [%0], [%1], 16;" :: "r"(s), "l"(g));
}
#define CP_COMMIT() asm volatile("cp.async.commit_group;")

// swizzled byte offset of element (row, k) in a [128][32] fp16 tile, 64B rows.
#define OFFS(row, k) ((uint32_t)((row) * 64 + ((((k) >> 3) ^ (((row) >> 1) & 3)) << 4)))

#define LDSM4(r, ad) \
    asm volatile("ldmatrix.sync.aligned.m8n8.x4.shared.b16 {%0,%1,%2,%3}, [%4];" \
        : "=r"((r)[0]), "=r"((r)[1]), "=r"((r)[2]), "=r"((r)[3]) : "r"(ad))

#define MMA(cc, A, b0, b1) \
    asm volatile("mma.sync.aligned.m16n8k16.row.col.f32.f16.f16.f32 " \
        "{%0,%1,%2,%3},{%4,%5,%6,%7},{%8,%9},{%0,%1,%2,%3};" \
        : "+f"((cc)[0]), "+f"((cc)[1]), "+f"((cc)[2]), "+f"((cc)[3]) \
        : "r"((A)[0]), "r"((A)[1]), "r"((A)[2]), "r"((A)[3]), "r"(b0), "r"(b1))

// static-index register access via dense switch (no local spill)
__device__ __forceinline__ void setreg(float* a, int i, float v) {
    switch (i) {
#define CS(J) case J: a[J] = v; break;
        CS(0) CS(1) CS(2) CS(3) CS(4) CS(5) CS(6) CS(7)
        CS(8) CS(9) CS(10) CS(11) CS(12) CS(13) CS(14) CS(15)
        CS(16) CS(17) CS(18) CS(19) CS(20) CS(21) CS(22) CS(23)
        CS(24) CS(25) CS(26) CS(27) CS(28) CS(29) CS(30) CS(31)
#undef CS
    }
}
__device__ __forceinline__ float getreg(const float* a, int i) {
    float v = 0.f;
    switch (i) {
#define CG(J) case J: v = a[J]; break;
        CG(0) CG(1) CG(2) CG(3) CG(4) CG(5) CG(6) CG(7)
        CG(8) CG(9) CG(10) CG(11) CG(12) CG(13) CG(14) CG(15)
        CG(16) CG(17) CG(18) CG(19) CG(20) CG(21) CG(22) CG(23)
        CG(24) CG(25) CG(26) CG(27) CG(28) CG(29) CG(30) CG(31)
#undef CG
    }
    return v;
}

// ===========================================================================
// prep: blocks 0-23 cayley (register GJ); blocks 24+ convert x -> fp16 split.
// ===========================================================================
__global__ __launch_bounds__(512)
void prep_kernel(const float* __restrict__ qR, const float* __restrict__ kR,
                 const float* __restrict__ vR, const float* __restrict__ x) {
    const int tid = threadIdx.x;
    if (blockIdx.x >= 24) {
        const float4* xv = (const float4*)x;
        const size_t stride = (size_t)1024 * 512;
        for (size_t u = (size_t)(blockIdx.x - 24) * 512 + tid;
             u < (size_t)32768 * 128; u += stride) {
            size_t m  = u >> 7;
            int    c8 = (int)(u & 127) * 8;
            float4 a = xv[2 * u];
            float4 b = xv[2 * u + 1];
            __half h0 = __float2half_rn(a.x), h1 = __float2half_rn(a.y);
            __half h2 = __float2half_rn(a.z), h3 = __float2half_rn(a.w);
            __half h4 = __float2half_rn(b.x), h5 = __float2half_rn(b.y);
            __half h6 = __float2half_rn(b.z), h7 = __float2half_rn(b.w);
            __half2 hv0 = __halves2half2(h0, h1), hv1 = __halves2half2(h2, h3);
            __half2 hv2 = __halves2half2(h4, h5), hv3 = __halves2half2(h6, h7);
            __half2 lv0 = __floats2half2_rn(a.x - __half2float(h0), a.y - __half2float(h1));
            __half2 lv1 = __floats2half2_rn(a.z - __half2float(h2), a.w - __half2float(h3));
            __half2 lv2 = __floats2half2_rn(b.x - __half2float(h4), b.y - __half2float(h5));
            __half2 lv3 = __floats2half2_rn(b.z - __half2float(h6), b.w - __half2float(h7));
            __half2* hp = (__half2*)&g_Ah[m * 2048 + c8];
            __half2* lp = (__half2*)&g_Ah[m * 2048 + 1024 + c8];
            hp[0] = hv0; hp[1] = hv1; hp[2] = hv2; hp[3] = hv3;
            lp[0] = lv0; lp[1] = lv1; lp[2] = lv2; lp[3] = lv3;
        }
        return;
    }
    // ---- cayley: Q = (2+eps)*inv(I+S+epsI) - I ----
    __shared__ float rowb[2][132];
    __shared__ float colb[2][128];
    const int idx  = blockIdx.x;
    const int proj = idx >> 3, n = idx & 7;
    const float* src = (proj == 0 ? qR : (proj == 1 ? kR : vR)) + n * 16384;
    const int r = tid & 127, q = tid >> 7, c0 = q * 32;

    float regs[32];
    #pragma unroll
    for (int j = 0; j < 32; ++j) {
        int c = c0 + j;
        float v = 0.5f * (src[r * 128 + c] - src[c * 128 + r]);
        if (c == r) v += 1.0f + EPSF;
        regs[j] = v;
    }
    if (r == 0) {
        #pragma unroll
        for (int j = 0; j < 32; ++j) rowb[0][c0 + j] = regs[j];
    }
    if (q == 0) colb[0][r] = regs[0];

    for (int k = 0; k < 128; ++k) {
        const int b = k & 1, nb = b ^ 1;
        __syncthreads();
        const float pivinv = 1.0f / rowb[b][k];
        const float f      = colb[b][r];
        const bool  own    = (q == (k >> 5));
        if (r == k) {
            #pragma unroll
            for (int j = 0; j < 32; ++j) regs[j] *= pivinv;
            if (own) setreg(regs, k & 31, pivinv);
        } else {
            const float t = f * pivinv;
            const float4* rp = (const float4*)&rowb[b][c0];
            #pragma unroll
            for (int v4 = 0; v4 < 8; ++v4) {
                float4 rv = rp[v4];
                regs[4 * v4 + 0] = fmaf(-t, rv.x, regs[4 * v4 + 0]);
                regs[4 * v4 + 1] = fmaf(-t, rv.y, regs[4 * v4 + 1]);
                regs[4 * v4 + 2] = fmaf(-t, rv.z, regs[4 * v4 + 2]);
                regs[4 * v4 + 3] = fmaf(-t, rv.w, regs[4 * v4 + 3]);
            }
            if (own) setreg(regs, k & 31, -t);
        }
        if (k < 127) {
            const int k1 = k + 1;
            if (r == k1) {
                float4* wp = (float4*)&rowb[nb][c0];
                #pragma unroll
                for (int v4 = 0; v4 < 8; ++v4)
                    wp[v4] = make_float4(regs[4 * v4 + 0], regs[4 * v4 + 1],
                                         regs[4 * v4 + 2], regs[4 * v4 + 3]);
            }
            if (q == (k1 >> 5)) colb[nb][r] = getreg(regs, k1 & 31);
        }
    }
    float* dst = g_Q + idx * 16384 + r * 128 + c0;
    const float s = 2.0f + EPSF;
    #pragma unroll
    for (int j = 0; j < 32; ++j) {
        float v = s * regs[j];
        if (c0 + j == r) v -= 1.0f;
        dst[j] = v;
    }
}

// ===========================================================================
// rotate: Wrot = W_block @ Q, single fp16 output. 192 CTAs.
// ===========================================================================
__global__ __launch_bounds__(256)
void rotate_kernel(const float* __restrict__ W) {
    extern __shared__ float Qs[];
    const int tid = threadIdx.x;
    const int b   = blockIdx.x;
    const int idx = b >> 3, oy = b & 7;
    const int proj = idx >> 3, n = idx & 7;
    const int obase = proj * 1024 + oy * 128;
    const int cbase = n * 128;
    for (int i = tid; i < 16384; i += 256) Qs[i] = g_Q[idx * 16384 + i];
    __syncthreads();
    const int c = tid & 127, half = tid >> 7;
    const float* Wp = W + (size_t)obase * 1024 + cbase;
    for (int oc = half * 64; oc < half * 64 + 64; oc += 4) {
        float acc[4] = {0.f, 0.f, 0.f, 0.f};
        #pragma unroll 4
        for (int bb = 0; bb < 128; ++bb) {
            float qv = Qs[bb * 128 + c];
            acc[0] = fmaf(Wp[(size_t)(oc + 0) * 1024 + bb], qv, acc[0]);
            acc[1] = fmaf(Wp[(size_t)(oc + 1) * 1024 + bb], qv, acc[1]);
            acc[2] = fmaf(Wp[(size_t)(oc + 2) * 1024 + bb], qv, acc[2]);
            acc[3] = fmaf(Wp[(size_t)(oc + 3) * 1024 + bb], qv, acc[3]);
        }
        #pragma unroll
        for (int u = 0; u < 4; ++u)
            g_Bh[(size_t)(obase + oc + u) * 1024 + cbase + c] = __float2half_rn(acc[u]);
    }
}

// ===========================================================================
// gemm: fp16 mma.sync 2-term split (Ahi*B + Alo*B). CTA 128x128, K chunks
// of 32, 3 stages (24KB each), one barrier per chunk.
// ===========================================================================
#define STAGE_B 24576
#define GEMM_SMEM (3 * STAGE_B)

__global__ __launch_bounds__(256, 2)
void gemm_kernel(const float* __restrict__ bias, float* __restrict__ out) {
    extern __shared__ char smem[];
    const uint32_t sb = smem_u32(smem);
    const int tid = threadIdx.x, wid = tid >> 5, lane = tid & 31;
    const int m0 = blockIdx.y * 128, n0 = blockIdx.x * 128;
    const int wm = (wid >> 2) * 64, wn = (wid & 3) * 32;

    float c[4][4][4];
    #pragma unroll
    for (int i = 0; i < 4; ++i)
        #pragma unroll
        for (int j = 0; j < 4; ++j)
            #pragma unroll
            for (int t = 0; t < 4; ++t) c[i][j][t] = 0.f;

    const int lrow0 = tid >> 2;
    const int lkg   = tid & 3;
    const uint32_t so0 = OFFS(lrow0, lkg * 8);
    const uint32_t so1 = OFFS(lrow0 + 64, lkg * 8);
    const char* gA0 = (const char*)g_Ah + (size_t)(m0 + lrow0) * 4096 + lkg * 16;
    const char* gA1 = gA0 + (size_t)64 * 4096;
    const char* gB0 = (const char*)g_Bh + (size_t)(n0 + lrow0) * 2048 + lkg * 16;
    const char* gB1 = gB0 + (size_t)64 * 2048;

#define ISSUE(kt) do { \
    uint32_t st = sb + ((kt) % 3) * STAGE_B; \
    size_t gk = (size_t)(kt) * 64; \
    cpa16(st + so0,         gA0 + gk); \
    cpa16(st + so1,         gA1 + gk); \
    cpa16(st +  8192 + so0, gA0 + gk + 2048); \
    cpa16(st +  8192 + so1, gA1 + gk + 2048); \
    cpa16(st + 16384 + so0, gB0 + gk); \
    cpa16(st + 16384 + so1, gB1 + gk); \
    CP_COMMIT(); \
} while (0)

#define KS_BODY(ks) do { \
    uint32_t a[4][4], bf[2][4]; \
    _Pragma("unroll") \
    for (int i = 0; i < 4; ++i) LDSM4(a[i], stAh + OFFS(arow + i * 16, (ks) + akb)); \
    _Pragma("unroll") \
    for (int p = 0; p < 2; ++p) LDSM4(bf[p], stB + OFFS(bnr + p * 16, (ks) + bkb)); \
    _Pragma("unroll") \
    for (int i = 0; i < 4; ++i) { \
        MMA(c[i][0], a[i], bf[0][0], bf[0][1]); \
        MMA(c[i][1], a[i], bf[0][2], bf[0][3]); \
        MMA(c[i][2], a[i], bf[1][0], bf[1][1]); \
        MMA(c[i][3], a[i], bf[1][2], bf[1][3]); \
    } \
    _Pragma("unroll") \
    for (int i = 0; i < 4; ++i) LDSM4(a[i], stAl + OFFS(arow + i * 16, (ks) + akb)); \
    _Pragma("unroll") \
    for (int i = 0; i < 4; ++i) { \
        MMA(c[i][0], a[i], bf[0][0], bf[0][1]); \
        MMA(c[i][1], a[i], bf[0][2], bf[0][3]); \
        MMA(c[i][2], a[i], bf[1][0], bf[1][1]); \
        MMA(c[i][3], a[i], bf[1][2], bf[1][3]); \
    } \
} while (0)

    ISSUE(0);
    ISSUE(1);

    const int arow = wm + (lane & 7) + ((lane >> 3) & 1) * 8;
    const int akb  = ((lane >> 4) & 1) * 8;
    const int bnr  = wn + (lane & 7) + ((lane >> 4) & 1) * 8;
    const int bkb  = ((lane >> 3) & 1) * 8;

    for (int kt = 0; kt < 32; ++kt) {
        if (kt < 31) asm volatile("cp.async.wait_group 1;");
        else         asm volatile("cp.async.wait_group 0;");
        __syncthreads();
        const uint32_t st   = sb + (kt % 3) * STAGE_B;
        const uint32_t stAh = st, stAl = st + 8192;
        const uint32_t stB  = st + 16384;

        KS_BODY(0);
        if (kt + 2 < 32) ISSUE(kt + 2);
        KS_BODY(16);
    }

    float2 bj[4];
    #pragma unroll
    for (int j = 0; j < 4; ++j)
        bj[j] = *(const float2*)(bias + n0 + wn + j * 8 + (lane & 3) * 2);

    #pragma unroll
    for (int i = 0; i < 4; ++i) {
        const int r = m0 + wm + i * 16 + (lane >> 2);
        #pragma unroll
        for (int j = 0; j < 4; ++j) {
            const int col = n0 + wn + j * 8 + (lane & 3) * 2;
            float2 v0 = {c[i][j][0] + bj[j].x, c[i][j][1] + bj[j].y};
            float2 v1 = {c[i][j][2] + bj[j].x, c[i][j][3] + bj[j].y};
            *(float2*)(out + (size_t)r * 3072 + col)       = v0;
            *(float2*)(out + (size_t)(r + 8) * 3072 + col) = v1;
        }
    }
}

// ---------------------------------------------------------------------------
extern "C" void kernel_launch(void* const* d_in, const int* in_sizes, int n_in,
                              void* d_out, int out_size) {
    const float* W    = (const float*)d_in[0];
    const float* bias = (const float*)d_in[1];
    const float* x    = (const float*)d_in[2];
    const float* qR   = (const float*)d_in[3];
    const float* kR   = (const float*)d_in[4];
    const float* vR   = (const float*)d_in[5];
    float* out = (float*)d_out;

    cudaFuncSetAttribute(rotate_kernel, cudaFuncAttributeMaxDynamicSharedMemorySize, 65536);
    cudaFuncSetAttribute(gemm_kernel,   cudaFuncAttributeMaxDynamicSharedMemorySize, GEMM_SMEM);

    prep_kernel<<<24 + 1024, 512>>>(qR, kR, vR, x);
    rotate_kernel<<<192, 256, 65536>>>(W);
    gemm_kernel<<<dim3(24, 256), 256, GEMM_SMEM>>>(bias, out);
}

// round 13
// speedup vs baseline: 6.3478x; 1.4803x over previous
#include <cuda_runtime.h>
#include <cuda_fp16.h>
#include <cstdint>

typedef unsigned long long ull;
#define EPSF 1e-6f

__device__ float   g_Q[24 * 128 * 128];
__device__ __half  g_Ah[(size_t)32768 * 1024];  // x as fp16
__device__ __half  g_Bh[(size_t)3072 * 1024];   // rotated W as fp16

__device__ __forceinline__ uint32_t smem_u32(const void* p) {
    uint32_t a;
    asm("{ .reg .u64 t; cvta.to.shared.u64 t, %1; cvt.u32.u64 %0, t; }" : "=r"(a) : "l"(p));
    return a;
}
__device__ __forceinline__ void cpa16(uint32_t s, const void* g) {
    asm volatile("cp.async.cg.shared.global [%0], [%1], 16;" :: "r"(s), "l"(g));
}
#define CP_COMMIT() asm volatile("cp.async.commit_group;")

// swizzled byte offset of element (row, k) in a [128][32] fp16 tile, 64B rows.
#define OFFS(row, k) ((uint32_t)((row) * 64 + ((((k) >> 3) ^ (((row) >> 1) & 3)) << 4)))

#define LDSM4(r, ad) \
    asm volatile("ldmatrix.sync.aligned.m8n8.x4.shared.b16 {%0,%1,%2,%3}, [%4];" \
        : "=r"((r)[0]), "=r"((r)[1]), "=r"((r)[2]), "=r"((r)[3]) : "r"(ad))

#define MMA(cc, A, b0, b1) \
    asm volatile("mma.sync.aligned.m16n8k16.row.col.f32.f16.f16.f32 " \
        "{%0,%1,%2,%3},{%4,%5,%6,%7},{%8,%9},{%0,%1,%2,%3};" \
        : "+f"((cc)[0]), "+f"((cc)[1]), "+f"((cc)[2]), "+f"((cc)[3]) \
        : "r"((A)[0]), "r"((A)[1]), "r"((A)[2]), "r"((A)[3]), "r"(b0), "r"(b1))

// static-index register access via dense switch (no local spill)
__device__ __forceinline__ void setreg(float* a, int i, float v) {
    switch (i) {
#define CS(J) case J: a[J] = v; break;
        CS(0) CS(1) CS(2) CS(3) CS(4) CS(5) CS(6) CS(7)
        CS(8) CS(9) CS(10) CS(11) CS(12) CS(13) CS(14) CS(15)
        CS(16) CS(17) CS(18) CS(19) CS(20) CS(21) CS(22) CS(23)
        CS(24) CS(25) CS(26) CS(27) CS(28) CS(29) CS(30) CS(31)
#undef CS
    }
}
__device__ __forceinline__ float getreg(const float* a, int i) {
    float v = 0.f;
    switch (i) {
#define CG(J) case J: v = a[J]; break;
        CG(0) CG(1) CG(2) CG(3) CG(4) CG(5) CG(6) CG(7)
        CG(8) CG(9) CG(10) CG(11) CG(12) CG(13) CG(14) CG(15)
        CG(16) CG(17) CG(18) CG(19) CG(20) CG(21) CG(22) CG(23)
        CG(24) CG(25) CG(26) CG(27) CG(28) CG(29) CG(30) CG(31)
#undef CG
    }
    return v;
}

// ===========================================================================
// prep: blocks 0-23 cayley (register GJ); blocks 24+ convert x -> fp16.
// ===========================================================================
__global__ __launch_bounds__(512)
void prep_kernel(const float* __restrict__ qR, const float* __restrict__ kR,
                 const float* __restrict__ vR, const float* __restrict__ x) {
    const int tid = threadIdx.x;
    if (blockIdx.x >= 24) {
        const float4* xv = (const float4*)x;
        const size_t stride = (size_t)1024 * 512;
        for (size_t u = (size_t)(blockIdx.x - 24) * 512 + tid;
             u < (size_t)32768 * 128; u += stride) {
            float4 a = xv[2 * u];
            float4 b = xv[2 * u + 1];
            uint4 hv;
            __half2 h0 = __floats2half2_rn(a.x, a.y);
            __half2 h1 = __floats2half2_rn(a.z, a.w);
            __half2 h2 = __floats2half2_rn(b.x, b.y);
            __half2 h3 = __floats2half2_rn(b.z, b.w);
            hv.x = *(uint32_t*)&h0; hv.y = *(uint32_t*)&h1;
            hv.z = *(uint32_t*)&h2; hv.w = *(uint32_t*)&h3;
            *(uint4*)(&g_Ah[u * 8]) = hv;
        }
        return;
    }
    // ---- cayley: Q = (2+eps)*inv(I+S+epsI) - I ----
    __shared__ float rowb[2][132];
    __shared__ float colb[2][128];
    const int idx  = blockIdx.x;
    const int proj = idx >> 3, n = idx & 7;
    const float* src = (proj == 0 ? qR : (proj == 1 ? kR : vR)) + n * 16384;
    const int r = tid & 127, q = tid >> 7, c0 = q * 32;

    float regs[32];
    #pragma unroll
    for (int j = 0; j < 32; ++j) {
        int c = c0 + j;
        float v = 0.5f * (src[r * 128 + c] - src[c * 128 + r]);
        if (c == r) v += 1.0f + EPSF;
        regs[j] = v;
    }
    if (r == 0) {
        #pragma unroll
        for (int j = 0; j < 32; ++j) rowb[0][c0 + j] = regs[j];
    }
    if (q == 0) colb[0][r] = regs[0];

    for (int k = 0; k < 128; ++k) {
        const int b = k & 1, nb = b ^ 1;
        __syncthreads();
        const float pivinv = 1.0f / rowb[b][k];
        const float f      = colb[b][r];
        const bool  own    = (q == (k >> 5));
        if (r == k) {
            #pragma unroll
            for (int j = 0; j < 32; ++j) regs[j] *= pivinv;
            if (own) setreg(regs, k & 31, pivinv);
        } else {
            const float t = f * pivinv;
            const float4* rp = (const float4*)&rowb[b][c0];
            #pragma unroll
            for (int v4 = 0; v4 < 8; ++v4) {
                float4 rv = rp[v4];
                regs[4 * v4 + 0] = fmaf(-t, rv.x, regs[4 * v4 + 0]);
                regs[4 * v4 + 1] = fmaf(-t, rv.y, regs[4 * v4 + 1]);
                regs[4 * v4 + 2] = fmaf(-t, rv.z, regs[4 * v4 + 2]);
                regs[4 * v4 + 3] = fmaf(-t, rv.w, regs[4 * v4 + 3]);
            }
            if (own) setreg(regs, k & 31, -t);
        }
        if (k < 127) {
            const int k1 = k + 1;
            if (r == k1) {
                float4* wp = (float4*)&rowb[nb][c0];
                #pragma unroll
                for (int v4 = 0; v4 < 8; ++v4)
                    wp[v4] = make_float4(regs[4 * v4 + 0], regs[4 * v4 + 1],
                                         regs[4 * v4 + 2], regs[4 * v4 + 3]);
            }
            if (q == (k1 >> 5)) colb[nb][r] = getreg(regs, k1 & 31);
        }
    }
    float* dst = g_Q + idx * 16384 + r * 128 + c0;
    const float s = 2.0f + EPSF;
    #pragma unroll
    for (int j = 0; j < 32; ++j) {
        float v = s * regs[j];
        if (c0 + j == r) v -= 1.0f;
        dst[j] = v;
    }
}

// ===========================================================================
// rotate: Wrot = W_block @ Q, fp16 output. 192 CTAs.
// ===========================================================================
__global__ __launch_bounds__(256)
void rotate_kernel(const float* __restrict__ W) {
    extern __shared__ float Qs[];
    const int tid = threadIdx.x;
    const int b   = blockIdx.x;
    const int idx = b >> 3, oy = b & 7;
    const int proj = idx >> 3, n = idx & 7;
    const int obase = proj * 1024 + oy * 128;
    const int cbase = n * 128;
    for (int i = tid; i < 16384; i += 256) Qs[i] = g_Q[idx * 16384 + i];
    __syncthreads();
    const int c = tid & 127, half = tid >> 7;
    const float* Wp = W + (size_t)obase * 1024 + cbase;
    for (int oc = half * 64; oc < half * 64 + 64; oc += 4) {
        float acc[4] = {0.f, 0.f, 0.f, 0.f};
        #pragma unroll 4
        for (int bb = 0; bb < 128; ++bb) {
            float qv = Qs[bb * 128 + c];
            acc[0] = fmaf(Wp[(size_t)(oc + 0) * 1024 + bb], qv, acc[0]);
            acc[1] = fmaf(Wp[(size_t)(oc + 1) * 1024 + bb], qv, acc[1]);
            acc[2] = fmaf(Wp[(size_t)(oc + 2) * 1024 + bb], qv, acc[2]);
            acc[3] = fmaf(Wp[(size_t)(oc + 3) * 1024 + bb], qv, acc[3]);
        }
        #pragma unroll
        for (int u = 0; u < 4; ++u)
            g_Bh[(size_t)(obase + oc + u) * 1024 + cbase + c] = __float2half_rn(acc[u]);
    }
}

// ===========================================================================
// gemm: single-pass fp16 mma.sync. CTA 128x128, K chunks of 32, 3 stages
// (16KB each), one barrier per chunk.
// ===========================================================================
#define STAGE_B 16384
#define GEMM_SMEM (3 * STAGE_B)

__global__ __launch_bounds__(256, 2)
void gemm_kernel(const float* __restrict__ bias, float* __restrict__ out) {
    extern __shared__ char smem[];
    const uint32_t sb = smem_u32(smem);
    const int tid = threadIdx.x, wid = tid >> 5, lane = tid & 31;
    const int m0 = blockIdx.y * 128, n0 = blockIdx.x * 128;
    const int wm = (wid >> 2) * 64, wn = (wid & 3) * 32;

    float c[4][4][4];
    #pragma unroll
    for (int i = 0; i < 4; ++i)
        #pragma unroll
        for (int j = 0; j < 4; ++j)
            #pragma unroll
            for (int t = 0; t < 4; ++t) c[i][j][t] = 0.f;

    const int lrow0 = tid >> 2;
    const int lkg   = tid & 3;
    const uint32_t so0 = OFFS(lrow0, lkg * 8);
    const uint32_t so1 = OFFS(lrow0 + 64, lkg * 8);
    const char* gA0 = (const char*)g_Ah + (size_t)(m0 + lrow0) * 2048 + lkg * 16;
    const char* gA1 = gA0 + (size_t)64 * 2048;
    const char* gB0 = (const char*)g_Bh + (size_t)(n0 + lrow0) * 2048 + lkg * 16;
    const char* gB1 = gB0 + (size_t)64 * 2048;

#define ISSUE(kt) do { \
    uint32_t st = sb + ((kt) % 3) * STAGE_B; \
    size_t gk = (size_t)(kt) * 64; \
    cpa16(st + so0,        gA0 + gk); \
    cpa16(st + so1,        gA1 + gk); \
    cpa16(st + 8192 + so0, gB0 + gk); \
    cpa16(st + 8192 + so1, gB1 + gk); \
    CP_COMMIT(); \
} while (0)

#define KS_BODY(ks) do { \
    uint32_t a[4][4], bf[2][4]; \
    _Pragma("unroll") \
    for (int i = 0; i < 4; ++i) LDSM4(a[i], stA + OFFS(arow + i * 16, (ks) + akb)); \
    _Pragma("unroll") \
    for (int p = 0; p < 2; ++p) LDSM4(bf[p], stB + OFFS(bnr + p * 16, (ks) + bkb)); \
    _Pragma("unroll") \
    for (int i = 0; i < 4; ++i) { \
        MMA(c[i][0], a[i], bf[0][0], bf[0][1]); \
        MMA(c[i][1], a[i], bf[0][2], bf[0][3]); \
        MMA(c[i][2], a[i], bf[1][0], bf[1][1]); \
        MMA(c[i][3], a[i], bf[1][2], bf[1][3]); \
    } \
} while (0)

    ISSUE(0);
    ISSUE(1);

    const int arow = wm + (lane & 7) + ((lane >> 3) & 1) * 8;
    const int akb  = ((lane >> 4) & 1) * 8;
    const int bnr  = wn + (lane & 7) + ((lane >> 4) & 1) * 8;
    const int bkb  = ((lane >> 3) & 1) * 8;

    for (int kt = 0; kt < 32; ++kt) {
        if (kt < 31) asm volatile("cp.async.wait_group 1;");
        else         asm volatile("cp.async.wait_group 0;");
        __syncthreads();
        const uint32_t stA = sb + (kt % 3) * STAGE_B;
        const uint32_t stB = stA + 8192;

        KS_BODY(0);
        if (kt + 2 < 32) ISSUE(kt + 2);
        KS_BODY(16);
    }

    float2 bj[4];
    #pragma unroll
    for (int j = 0; j < 4; ++j)
        bj[j] = *(const float2*)(bias + n0 + wn + j * 8 + (lane & 3) * 2);

    #pragma unroll
    for (int i = 0; i < 4; ++i) {
        const int r = m0 + wm + i * 16 + (lane >> 2);
        #pragma unroll
        for (int j = 0; j < 4; ++j) {
            const int col = n0 + wn + j * 8 + (lane & 3) * 2;
            float2 v0 = {c[i][j][0] + bj[j].x, c[i][j][1] + bj[j].y};
            float2 v1 = {c[i][j][2] + bj[j].x, c[i][j][3] + bj[j].y};
            *(float2*)(out + (size_t)r * 3072 + col)       = v0;
            *(float2*)(out + (size_t)(r + 8) * 3072 + col) = v1;
        }
    }
}

// ---------------------------------------------------------------------------
extern "C" void kernel_launch(void* const* d_in, const int* in_sizes, int n_in,
                              void* d_out, int out_size) {
    const float* W    = (const float*)d_in[0];
    const float* bias = (const float*)d_in[1];
    const float* x    = (const float*)d_in[2];
    const float* qR   = (const float*)d_in[3];
    const float* kR   = (const float*)d_in[4];
    const float* vR   = (const float*)d_in[5];
    float* out = (float*)d_out;

    cudaFuncSetAttribute(rotate_kernel, cudaFuncAttributeMaxDynamicSharedMemorySize, 65536);
    cudaFuncSetAttribute(gemm_kernel,   cudaFuncAttributeMaxDynamicSharedMemorySize, GEMM_SMEM);

    prep_kernel<<<24 + 1024, 512>>>(qR, kR, vR, x);
    rotate_kernel<<<192, 256, 65536>>>(W);
    gemm_kernel<<<dim3(24, 256), 256, GEMM_SMEM>>>(bias, out);
}

// round 14
// speedup vs baseline: 6.8001x; 1.0713x over previous
#include <cuda_runtime.h>
#include <cuda_fp16.h>
#include <cstdint>

typedef unsigned long long ull;
#define EPSF 1e-6f

__device__ float   g_Q[24 * 128 * 128];
__device__ __half  g_Ah[(size_t)32768 * 1024];  // x as fp16
__device__ __half  g_Bh[(size_t)3072 * 1024];   // rotated W as fp16

__device__ __forceinline__ uint32_t smem_u32(const void* p) {
    uint32_t a;
    asm("{ .reg .u64 t; cvta.to.shared.u64 t, %1; cvt.u32.u64 %0, t; }" : "=r"(a) : "l"(p));
    return a;
}
__device__ __forceinline__ void cpa16(uint32_t s, const void* g) {
    asm volatile("cp.async.cg.shared.global [%0], [%1], 16;" :: "r"(s), "l"(g));
}
#define CP_COMMIT() asm volatile("cp.async.commit_group;")

// swizzled byte offset of element (row, k) in a [128][64] fp16 tile, 128B rows.
#define OFFS64(row, k) ((uint32_t)((row) * 128 + (((((k) >> 3) ^ ((row) & 7))) << 4)))

#define LDSM4(r, ad) \
    asm volatile("ldmatrix.sync.aligned.m8n8.x4.shared.b16 {%0,%1,%2,%3}, [%4];" \
        : "=r"((r)[0]), "=r"((r)[1]), "=r"((r)[2]), "=r"((r)[3]) : "r"(ad))

#define MMA(cc, A, b0, b1) \
    asm volatile("mma.sync.aligned.m16n8k16.row.col.f32.f16.f16.f32 " \
        "{%0,%1,%2,%3},{%4,%5,%6,%7},{%8,%9},{%0,%1,%2,%3};" \
        : "+f"((cc)[0]), "+f"((cc)[1]), "+f"((cc)[2]), "+f"((cc)[3]) \
        : "r"((A)[0]), "r"((A)[1]), "r"((A)[2]), "r"((A)[3]), "r"(b0), "r"(b1))

// ===========================================================================
// prep: blocks 0-23 cayley (register GJ, static unroll); blocks 24+ convert.
// ===========================================================================
__global__ __launch_bounds__(512)
void prep_kernel(const float* __restrict__ qR, const float* __restrict__ kR,
                 const float* __restrict__ vR, const float* __restrict__ x) {
    const int tid = threadIdx.x;
    if (blockIdx.x >= 24) {
        const float4* xv = (const float4*)x;
        const size_t stride = (size_t)1024 * 512;
        for (size_t u = (size_t)(blockIdx.x - 24) * 512 + tid;
             u < (size_t)32768 * 128; u += stride) {
            float4 a = xv[2 * u];
            float4 b = xv[2 * u + 1];
            uint4 hv;
            __half2 h0 = __floats2half2_rn(a.x, a.y);
            __half2 h1 = __floats2half2_rn(a.z, a.w);
            __half2 h2 = __floats2half2_rn(b.x, b.y);
            __half2 h3 = __floats2half2_rn(b.z, b.w);
            hv.x = *(uint32_t*)&h0; hv.y = *(uint32_t*)&h1;
            hv.z = *(uint32_t*)&h2; hv.w = *(uint32_t*)&h3;
            *(uint4*)(&g_Ah[u * 8]) = hv;
        }
        return;
    }
    // ---- cayley: Q = (2+eps)*inv(I+S+epsI) - I ----
    __shared__ float rowb[2][132];
    __shared__ float colb[2][128];
    const int idx  = blockIdx.x;
    const int proj = idx >> 3, n = idx & 7;
    const float* src = (proj == 0 ? qR : (proj == 1 ? kR : vR)) + n * 16384;
    const int r = tid & 127, q = tid >> 7, c0 = q * 32;

    float regs[32];
    #pragma unroll
    for (int j = 0; j < 32; ++j) {
        int c = c0 + j;
        float v = 0.5f * (src[r * 128 + c] - src[c * 128 + r]);
        if (c == r) v += 1.0f + EPSF;
        regs[j] = v;
    }
    if (r == 0) {
        #pragma unroll
        for (int j = 0; j < 32; ++j) rowb[0][c0 + j] = regs[j];
    }
    if (q == 0) colb[0][r] = regs[0];

    for (int kb = 0; kb < 4; ++kb) {
        const bool ownq  = (q == kb);
        const bool nextq = (q == kb + 1);
        #pragma unroll
        for (int kk = 0; kk < 32; ++kk) {
            const int k = kb * 32 + kk;
            const int b = k & 1, nb = b ^ 1;
            __syncthreads();
            const float pivinv = 1.0f / rowb[b][k];
            const float f      = colb[b][r];
            if (r == k) {
                #pragma unroll
                for (int j = 0; j < 32; ++j) regs[j] *= pivinv;
                if (ownq) regs[kk] = pivinv;
            } else {
                const float t = f * pivinv;
                const float4* rp = (const float4*)&rowb[b][c0];
                #pragma unroll
                for (int v4 = 0; v4 < 8; ++v4) {
                    float4 rv = rp[v4];
                    regs[4 * v4 + 0] = fmaf(-t, rv.x, regs[4 * v4 + 0]);
                    regs[4 * v4 + 1] = fmaf(-t, rv.y, regs[4 * v4 + 1]);
                    regs[4 * v4 + 2] = fmaf(-t, rv.z, regs[4 * v4 + 2]);
                    regs[4 * v4 + 3] = fmaf(-t, rv.w, regs[4 * v4 + 3]);
                }
                if (ownq) regs[kk] = -t;
            }
            if (k < 127) {
                if (r == k + 1) {
                    float4* wp = (float4*)&rowb[nb][c0];
                    #pragma unroll
                    for (int v4 = 0; v4 < 8; ++v4)
                        wp[v4] = make_float4(regs[4 * v4 + 0], regs[4 * v4 + 1],
                                             regs[4 * v4 + 2], regs[4 * v4 + 3]);
                }
                if (kk < 31) { if (ownq)  colb[nb][r] = regs[kk + 1]; }
                else         { if (nextq) colb[nb][r] = regs[0]; }
            }
        }
    }
    float* dst = g_Q + idx * 16384 + r * 128 + c0;
    const float s = 2.0f + EPSF;
    #pragma unroll
    for (int j = 0; j < 32; ++j) {
        float v = s * regs[j];
        if (c0 + j == r) v -= 1.0f;
        dst[j] = v;
    }
}

// ===========================================================================
// rotate: Wrot = W_block @ Q, fp16 output. 192 CTAs.
// ===========================================================================
__global__ __launch_bounds__(256)
void rotate_kernel(const float* __restrict__ W) {
    extern __shared__ float Qs[];
    const int tid = threadIdx.x;
    const int b   = blockIdx.x;
    const int idx = b >> 3, oy = b & 7;
    const int proj = idx >> 3, n = idx & 7;
    const int obase = proj * 1024 + oy * 128;
    const int cbase = n * 128;
    for (int i = tid; i < 16384; i += 256) Qs[i] = g_Q[idx * 16384 + i];
    __syncthreads();
    const int c = tid & 127, half = tid >> 7;
    const float* Wp = W + (size_t)obase * 1024 + cbase;
    for (int oc = half * 64; oc < half * 64 + 64; oc += 4) {
        float acc[4] = {0.f, 0.f, 0.f, 0.f};
        #pragma unroll 4
        for (int bb = 0; bb < 128; ++bb) {
            float qv = Qs[bb * 128 + c];
            acc[0] = fmaf(Wp[(size_t)(oc + 0) * 1024 + bb], qv, acc[0]);
            acc[1] = fmaf(Wp[(size_t)(oc + 1) * 1024 + bb], qv, acc[1]);
            acc[2] = fmaf(Wp[(size_t)(oc + 2) * 1024 + bb], qv, acc[2]);
            acc[3] = fmaf(Wp[(size_t)(oc + 3) * 1024 + bb], qv, acc[3]);
        }
        #pragma unroll
        for (int u = 0; u < 4; ++u)
            g_Bh[(size_t)(obase + oc + u) * 1024 + cbase + c] = __float2half_rn(acc[u]);
    }
}

// ===========================================================================
// gemm: single-pass fp16 mma.sync. CTA 128x128, K chunks of 64, 3 stages
// (32KB each), one barrier per chunk (16 barriers total).
// ===========================================================================
#define STAGE_B 32768
#define GEMM_SMEM (3 * STAGE_B)

__global__ __launch_bounds__(256, 2)
void gemm_kernel(const float* __restrict__ bias, float* __restrict__ out) {
    extern __shared__ char smem[];
    const uint32_t sb = smem_u32(smem);
    const int tid = threadIdx.x, wid = tid >> 5, lane = tid & 31;
    const int m0 = blockIdx.y * 128, n0 = blockIdx.x * 128;
    const int wm = (wid >> 2) * 64, wn = (wid & 3) * 32;

    float c[4][4][4];
    #pragma unroll
    for (int i = 0; i < 4; ++i)
        #pragma unroll
        for (int j = 0; j < 4; ++j)
            #pragma unroll
            for (int t = 0; t < 4; ++t) c[i][j][t] = 0.f;

    // loader geometry: per u, id = tid + 256u -> row = id>>3 (0..127), kg = id&7
    uint32_t soU[4];
    const char* gAu[4];
    const char* gBu[4];
    #pragma unroll
    for (int u = 0; u < 4; ++u) {
        int id  = tid + 256 * u;
        int row = id >> 3, kg = id & 7;
        soU[u] = (uint32_t)(row * 128 + ((kg ^ (row & 7)) << 4));
        gAu[u] = (const char*)g_Ah + (size_t)(m0 + row) * 2048 + kg * 16;
        gBu[u] = (const char*)g_Bh + (size_t)(n0 + row) * 2048 + kg * 16;
    }

#define ISSUE(kt) do { \
    uint32_t st = sb + ((kt) % 3) * STAGE_B; \
    size_t gk = (size_t)(kt) * 128; \
    _Pragma("unroll") \
    for (int u = 0; u < 4; ++u) { \
        cpa16(st + soU[u],         gAu[u] + gk); \
        cpa16(st + 16384 + soU[u], gBu[u] + gk); \
    } \
    CP_COMMIT(); \
} while (0)

#define KS_BODY(ks) do { \
    uint32_t a[4][4], bf[2][4]; \
    _Pragma("unroll") \
    for (int i = 0; i < 4; ++i) LDSM4(a[i], stA + OFFS64(arow + i * 16, (ks) + akb)); \
    _Pragma("unroll") \
    for (int p = 0; p < 2; ++p) LDSM4(bf[p], stB + OFFS64(bnr + p * 16, (ks) + bkb)); \
    _Pragma("unroll") \
    for (int i = 0; i < 4; ++i) { \
        MMA(c[i][0], a[i], bf[0][0], bf[0][1]); \
        MMA(c[i][1], a[i], bf[0][2], bf[0][3]); \
        MMA(c[i][2], a[i], bf[1][0], bf[1][1]); \
        MMA(c[i][3], a[i], bf[1][2], bf[1][3]); \
    } \
} while (0)

    ISSUE(0);
    ISSUE(1);

    const int arow = wm + (lane & 7) + ((lane >> 3) & 1) * 8;
    const int akb  = ((lane >> 4) & 1) * 8;
    const int bnr  = wn + (lane & 7) + ((lane >> 4) & 1) * 8;
    const int bkb  = ((lane >> 3) & 1) * 8;

    for (int kt = 0; kt < 16; ++kt) {
        if (kt < 15) asm volatile("cp.async.wait_group 1;");
        else         asm volatile("cp.async.wait_group 0;");
        __syncthreads();
        const uint32_t stA = sb + (kt % 3) * STAGE_B;
        const uint32_t stB = stA + 16384;

        KS_BODY(0);
        KS_BODY(16);
        if (kt + 2 < 16) ISSUE(kt + 2);
        KS_BODY(32);
        KS_BODY(48);
    }

    float2 bj[4];
    #pragma unroll
    for (int j = 0; j < 4; ++j)
        bj[j] = *(const float2*)(bias + n0 + wn + j * 8 + (lane & 3) * 2);

    #pragma unroll
    for (int i = 0; i < 4; ++i) {
        const int r = m0 + wm + i * 16 + (lane >> 2);
        #pragma unroll
        for (int j = 0; j < 4; ++j) {
            const int col = n0 + wn + j * 8 + (lane & 3) * 2;
            float2 v0 = {c[i][j][0] + bj[j].x, c[i][j][1] + bj[j].y};
            float2 v1 = {c[i][j][2] + bj[j].x, c[i][j][3] + bj[j].y};
            *(float2*)(out + (size_t)r * 3072 + col)       = v0;
            *(float2*)(out + (size_t)(r + 8) * 3072 + col) = v1;
        }
    }
}

// ---------------------------------------------------------------------------
extern "C" void kernel_launch(void* const* d_in, const int* in_sizes, int n_in,
                              void* d_out, int out_size) {
    const float* W    = (const float*)d_in[0];
    const float* bias = (const float*)d_in[1];
    const float* x    = (const float*)d_in[2];
    const float* qR   = (const float*)d_in[3];
    const float* kR   = (const float*)d_in[4];
    const float* vR   = (const float*)d_in[5];
    float* out = (float*)d_out;

    cudaFuncSetAttribute(rotate_kernel, cudaFuncAttributeMaxDynamicSharedMemorySize, 65536);
    cudaFuncSetAttribute(gemm_kernel,   cudaFuncAttributeMaxDynamicSharedMemorySize, GEMM_SMEM);

    prep_kernel<<<24 + 1024, 512>>>(qR, kR, vR, x);
    rotate_kernel<<<192, 256, 65536>>>(W);
    gemm_kernel<<<dim3(24, 256), 256, GEMM_SMEM>>>(bias, out);
}